// round 13
// baseline (speedup 1.0000x reference)
#include <cuda_runtime.h>
#include <cuda_bf16.h>
#include <math.h>
#include <stddef.h>
#include <stdint.h>

#define Bsz 256
#define Dd  512
#define Hh  512
#define Uu  24
#define Kk  8
#define IKk 64
#define IVv 400
#define IVP 416        // IVv padded to multiple of 32
#define CKk 32
#define NCHh 4
#define CVv 512

typedef __nv_bfloat16 bf16;

// ---------------- fp32 scratch ----------------
__device__ float g_k0[Bsz * IKk];
__device__ float g_v0[Bsz * IVv];
__device__ float g_s0[Bsz * Uu];
__device__ float g_p0[Bsz * Uu];
__device__ float g_mask[Bsz * Uu];
__device__ float g_pre[(size_t)Bsz * Uu * 4 * Hh];   // 50 MB
__device__ float g_ht[Bsz * Uu * Hh];
__device__ float g_qc[Bsz * Uu * NCHh * CKk];
__device__ float g_kc[Bsz * Uu * NCHh * CKk];
__device__ float g_vc[(size_t)Bsz * Uu * NCHh * CVv];  // 50 MB

// ---------------- bf16 hi/lo activations (A operands) -------------
__device__ __align__(16) bf16 g_inp_h[Bsz * Uu * IVP];
__device__ __align__(16) bf16 g_inp_l[Bsz * Uu * IVP];
__device__ __align__(16) bf16 g_hs_h[Bsz * Uu * Hh];
__device__ __align__(16) bf16 g_hs_l[Bsz * Uu * Hh];
__device__ __align__(16) bf16 g_hth[Bsz * Uu * Hh];
__device__ __align__(16) bf16 g_htl[Bsz * Uu * Hh];
__device__ __align__(16) bf16 g_ctx_h[(size_t)Bsz * Uu * NCHh * CVv];
__device__ __align__(16) bf16 g_ctx_l[(size_t)Bsz * Uu * NCHh * CVv];

// ===================== PTX helpers (baseline sm_80+ only) =====================
__device__ __forceinline__ uint32_t smem_u32(const void* p) {
    uint32_t a;
    asm("{ .reg .u64 t; cvta.to.shared.u64 t, %1; cvt.u32.u64 %0, t; }" : "=r"(a) : "l"(p));
    return a;
}
__device__ __forceinline__ void cp16(uint32_t dst, const void* src) {
    asm volatile("cp.async.cg.shared.global [%0], [%1], 16;"
                 :: "r"(dst), "l"(__cvta_generic_to_global(src)) : "memory");
}
__device__ __forceinline__ void cp_commit() {
    asm volatile("cp.async.commit_group;" ::: "memory");
}
__device__ __forceinline__ void cp_wait0() {
    asm volatile("cp.async.wait_group 0;" ::: "memory");
}
__device__ __forceinline__ void cp_wait1() {
    asm volatile("cp.async.wait_group 1;" ::: "memory");
}
__device__ __forceinline__ void ldsm_x4(uint32_t* r, uint32_t addr) {
    asm volatile("ldmatrix.sync.aligned.m8n8.x4.shared.b16 {%0,%1,%2,%3}, [%4];"
                 : "=r"(r[0]), "=r"(r[1]), "=r"(r[2]), "=r"(r[3]) : "r"(addr));
}
__device__ __forceinline__ void ldsm_x2_trans(uint32_t* r, uint32_t addr) {
    asm volatile("ldmatrix.sync.aligned.m8n8.x2.trans.shared.b16 {%0,%1}, [%2];"
                 : "=r"(r[0]), "=r"(r[1]) : "r"(addr));
}
__device__ __forceinline__ void mma_bf16(float* d, const uint32_t* a, const uint32_t* b) {
    asm volatile(
        "mma.sync.aligned.m16n8k16.row.col.f32.bf16.bf16.f32 "
        "{%0,%1,%2,%3}, {%4,%5,%6,%7}, {%8,%9}, {%0,%1,%2,%3};"
        : "+f"(d[0]), "+f"(d[1]), "+f"(d[2]), "+f"(d[3])
        : "r"(a[0]), "r"(a[1]), "r"(a[2]), "r"(a[3]), "r"(b[0]), "r"(b[1]));
}

// ---------------- stage A: k0 = x@key_w+key_b, v0 = x@value_w+value_b ------
__global__ void kv_kernel(const float* __restrict__ x,
                          const float* __restrict__ key_w, const float* __restrict__ key_b,
                          const float* __restrict__ value_w, const float* __restrict__ value_b) {
    int b = blockIdx.x;
    __shared__ float xs[Dd];
    int tid = threadIdx.x; // 512
    xs[tid] = x[(size_t)b * Dd + tid];
    __syncthreads();
    if (tid < IVv) {
        float acc = value_b[tid];
        #pragma unroll 8
        for (int d = 0; d < Dd; d++) acc += xs[d] * value_w[(size_t)d * IVv + tid];
        g_v0[b * IVv + tid] = acc;
    } else if (tid < IVv + IKk) {
        int ik = tid - IVv;
        float acc = key_b[ik];
        #pragma unroll 8
        for (int d = 0; d < Dd; d++) acc += xs[d] * key_w[(size_t)d * IKk + ik];
        g_k0[b * IKk + ik] = acc;
    }
}

// ---------------- stage A: q, scores, probs ----------------
__global__ void qscore_kernel(const float* __restrict__ hs,
                              const float* __restrict__ query_w,
                              const float* __restrict__ key_b) {
    int bu = blockIdx.x;
    int b = bu / Uu, u = bu % Uu;
    int ik = threadIdx.x; // 64
    __shared__ float hss[Hh];
    for (int i = ik; i < Hh; i += 64) hss[i] = hs[(size_t)bu * Hh + i];
    __syncthreads();
    const float* qw = query_w + (size_t)u * Hh * IKk;
    float q = 0.f;
    #pragma unroll 8
    for (int d = 0; d < Hh; d++) q += hss[d] * qw[(size_t)d * IKk + ik];
    float p0 = q * g_k0[b * IKk + ik];
    float p1 = q * key_b[ik];
    #pragma unroll
    for (int off = 16; off > 0; off >>= 1) {
        p0 += __shfl_down_sync(0xffffffffu, p0, off);
        p1 += __shfl_down_sync(0xffffffffu, p1, off);
    }
    __shared__ float r0[2], r1[2];
    if ((ik & 31) == 0) { r0[ik >> 5] = p0; r1[ik >> 5] = p1; }
    __syncthreads();
    if (ik == 0) {
        float s0 = (r0[0] + r0[1]) * 0.125f;
        float s1 = (r1[0] + r1[1]) * 0.125f;
        g_s0[bu] = s0;
        float m = fmaxf(s0, s1);
        float e0 = expf(s0 - m), e1 = expf(s1 - m);
        g_p0[bu] = e0 / (e0 + e1);
    }
}

// ---------------- top-k mask ----------------
__global__ void topk_kernel() {
    int b = threadIdx.x;
    float s[Uu];
    #pragma unroll
    for (int u = 0; u < Uu; u++) s[u] = g_s0[b * Uu + u];
    #pragma unroll
    for (int u = 0; u < Uu; u++) {
        int cnt = 0;
        #pragma unroll
        for (int t = 0; t < Uu; t++)
            if (s[t] > s[u] || (s[t] == s[u] && t < u)) cnt++;
        g_mask[b * Uu + u] = (cnt < Kk) ? 1.f : 0.f;
    }
}

// ---------------- inp (bf16 hi/lo out, padded K to 416) ----------------
__global__ void inp_kernel(const float* __restrict__ value_b) {
    int idx = blockIdx.x * blockDim.x + threadIdx.x;
    if (idx >= Bsz * Uu * IVP) return;
    int iv = idx % IVP;
    int bu = idx / IVP;
    int b = bu / Uu;
    float v = 0.f;
    if (iv < IVv) {
        float p0 = g_p0[bu];
        v = p0 * g_v0[b * IVv + iv] + (1.f - p0) * value_b[iv];
        v *= g_mask[bu];
    }
    bf16 h = __float2bfloat16_rn(v);
    g_inp_h[idx] = h;
    g_inp_l[idx] = __float2bfloat16_rn(v - __bfloat162float(h));
}

// ---------------- hs -> bf16 hi/lo ----------------
__global__ void hsconv_kernel(const float* __restrict__ hs) {
    int idx = blockIdx.x * blockDim.x + threadIdx.x;
    if (idx >= Bsz * Uu * Hh) return;
    float v = hs[idx];
    bf16 h = __float2bfloat16_rn(v);
    g_hs_h[idx] = h;
    g_hs_l[idx] = __float2bfloat16_rn(v - __bfloat162float(h));
}

// ===================== bf16-split tensor-core GEMM (mma.sync) =====================
// D[(b*U+u)*ldc + n] = sum_k A(b,u,k) * W[u][k][n], hi/lo split, fp32 acc.
// Weights consumed DIRECTLY as f32 [u][K][N]: LDG.128 prefetch -> in-register
// hi/lo bf16 split -> STS into padded row-major tiles -> ldmatrix.trans.
// CTA 128x128, 8 warps (2Mx4N), BK=32, A via cp.async (bf16 hi/lo activations).
// mode 0: store C. mode 1: out = mask ? acc+ht : hs_in. mode 2: blockIdx.x picks
//         (Bw1,C) vs (Bw2,C2), n0=0, single pass.
#define BKc   32
#define BKp   40
#define BNp   136
#define AST   (128 * BKp * 2)     // 10240 B per A tile
#define BST   (BKc * BNp * 2)     // 8704 B per B tile
#define STAGE (2 * AST + 2 * BST) // 37888 B
#define SMEMT (2 * STAGE)         // 75776 B

extern __shared__ char gsm[];

struct GArgs {
    const bf16 *Auh, *Aul;
    const float *Bw;          // native f32 weights, offset by u and n0
    int K, Kreal, ars, ldw;
};

__device__ __forceinline__ void issue_A(const GArgs& ga, uint32_t sbuf,
                                        int k0, int tid) {
    #pragma unroll
    for (int h = 0; h < 2; h++) {
        int c = tid + h * 256;
        int arow = c >> 2, aseg = c & 3;
        uint32_t ad = sbuf + (uint32_t)(arow * (BKp * 2) + aseg * 16);
        cp16(ad,       ga.Auh + (size_t)arow * ga.ars + k0 + aseg * 8);
        cp16(ad + AST, ga.Aul + (size_t)arow * ga.ars + k0 + aseg * 8);
    }
    cp_commit();
}

// LDG prefetch of one 32x128 f32 B tile (16 f32/thread)
__device__ __forceinline__ void ldg_B(const GArgs& ga, int k0, int tid, float4* br) {
    #pragma unroll
    for (int h = 0; h < 4; h++) {
        int c = tid + h * 256;
        int row = c >> 5, seg = c & 31;
        if (k0 + row < ga.Kreal)
            br[h] = *(const float4*)(ga.Bw + (size_t)(k0 + row) * ga.ldw + seg * 4);
        else
            br[h] = make_float4(0.f, 0.f, 0.f, 0.f);
    }
}

// convert + store the prefetched tile into smem hi/lo B tiles
__device__ __forceinline__ void sts_B(char* bufB, int tid, const float4* br) {
    #pragma unroll
    for (int h = 0; h < 4; h++) {
        int c = tid + h * 256;
        int row = c >> 5, seg = c & 31;
        float4 v = br[h];
        bf16 h0 = __float2bfloat16_rn(v.x), h1 = __float2bfloat16_rn(v.y);
        bf16 h2 = __float2bfloat16_rn(v.z), h3 = __float2bfloat16_rn(v.w);
        bf16 l0 = __float2bfloat16_rn(v.x - __bfloat162float(h0));
        bf16 l1 = __float2bfloat16_rn(v.y - __bfloat162float(h1));
        bf16 l2 = __float2bfloat16_rn(v.z - __bfloat162float(h2));
        bf16 l3 = __float2bfloat16_rn(v.w - __bfloat162float(h3));
        uint2 ph, pl;
        ph.x = (uint32_t)__bfloat16_as_ushort(h0) | ((uint32_t)__bfloat16_as_ushort(h1) << 16);
        ph.y = (uint32_t)__bfloat16_as_ushort(h2) | ((uint32_t)__bfloat16_as_ushort(h3) << 16);
        pl.x = (uint32_t)__bfloat16_as_ushort(l0) | ((uint32_t)__bfloat16_as_ushort(l1) << 16);
        pl.y = (uint32_t)__bfloat16_as_ushort(l2) | ((uint32_t)__bfloat16_as_ushort(l3) << 16);
        char* p = bufB + row * (BNp * 2) + seg * 8;
        *(uint2*)p         = ph;
        *(uint2*)(p + BST) = pl;
    }
}

__global__ void __launch_bounds__(256) bgemm(
    const bf16* __restrict__ Ah1, const bf16* __restrict__ Al1, int a1_uoff, int a1_rs,
    const float* __restrict__ Bw1, int K1, int K1real,
    const bf16* __restrict__ Ah2, const bf16* __restrict__ Al2, int a2_uoff, int a2_rs,
    const float* __restrict__ Bw2, int K2, int K2real,
    int ldc, float* __restrict__ C, int mode, float* __restrict__ C2,
    const float* __restrict__ ht, const float* __restrict__ mk,
    const float* __restrict__ hs_in, float* __restrict__ outp)
{
    uint32_t sb = smem_u32(gsm);
    int tid  = threadIdx.x;
    int lane = tid & 31, wid = tid >> 5;
    int wm = wid & 1, wn = wid >> 1;
    int u = blockIdx.z, m0 = blockIdx.y * 128;
    int n0;
    const float* Bw = Bw1;
    float* Csel = C;
    if (mode == 2) {
        n0 = 0;
        if (blockIdx.x) { Bw = Bw2; Csel = C2; }
    } else {
        n0 = blockIdx.x * 128;
    }

    float acc[4][4][4];
    #pragma unroll
    for (int i = 0; i < 4; i++)
        #pragma unroll
        for (int j = 0; j < 4; j++)
            #pragma unroll
            for (int k = 0; k < 4; k++) acc[i][j][k] = 0.f;

    int a_ro = lane & 15, a_cg = lane >> 4;
    int b_kr = (lane & 7) + 8 * ((lane >> 3) & 1);

    int npass = (mode != 2 && K2 > 0) ? 2 : 1;
    #pragma unroll 1
    for (int pass = 0; pass < npass; pass++) {
        GArgs ga;
        if (pass == 0) {
            ga.Auh = Ah1 + (size_t)u * a1_uoff + (size_t)m0 * a1_rs;
            ga.Aul = Al1 + (size_t)u * a1_uoff + (size_t)m0 * a1_rs;
            ga.Bw  = Bw + (size_t)u * K1real * ldc + n0;
            ga.K = K1; ga.Kreal = K1real; ga.ars = a1_rs; ga.ldw = ldc;
        } else {
            ga.Auh = Ah2 + (size_t)u * a2_uoff + (size_t)m0 * a2_rs;
            ga.Aul = Al2 + (size_t)u * a2_uoff + (size_t)m0 * a2_rs;
            ga.Bw  = Bw2 + (size_t)u * K2real * ldc + n0;
            ga.K = K2; ga.Kreal = K2real; ga.ars = a2_rs; ga.ldw = ldc;
        }
        int T = ga.K / BKc;

        float4 br[4];
        // prologue: tile 0
        ldg_B(ga, 0, tid, br);
        issue_A(ga, sb, 0, tid);
        sts_B(gsm + 2 * AST, tid, br);

        #pragma unroll 1
        for (int t = 0; t < T; t++) {
            uint32_t scur = sb + (uint32_t)((t & 1) * STAGE);
            char* bnxt = gsm + ((t + 1) & 1) * STAGE + 2 * AST;
            if (t + 1 < T) {
                ldg_B(ga, (t + 1) * BKc, tid, br);
                issue_A(ga, sb + (uint32_t)(((t + 1) & 1) * STAGE), (t + 1) * BKc, tid);
                cp_wait1();
            } else {
                cp_wait0();
            }
            __syncthreads();   // current stage (A cp.async + B STS) ready

            #pragma unroll
            for (int ks = 0; ks < 2; ks++) {
                int koff = ks * 16;
                uint32_t a_h[4][4], a_l[4][4], b_h[4][2], b_l[4][2];
                #pragma unroll
                for (int mt = 0; mt < 4; mt++) {
                    uint32_t ad = scur +
                        (uint32_t)(((wm * 64 + mt * 16 + a_ro) * BKp + koff + a_cg * 8) * 2);
                    ldsm_x4(a_h[mt], ad);
                    ldsm_x4(a_l[mt], ad + AST);
                }
                #pragma unroll
                for (int nt = 0; nt < 4; nt++) {
                    uint32_t bd = scur + 2 * AST +
                        (uint32_t)(((koff + b_kr) * BNp + wn * 32 + nt * 8) * 2);
                    ldsm_x2_trans(b_h[nt], bd);
                    ldsm_x2_trans(b_l[nt], bd + BST);
                }
                #pragma unroll
                for (int mt = 0; mt < 4; mt++)
                    #pragma unroll
                    for (int nt = 0; nt < 4; nt++)
                        mma_bf16(acc[mt][nt], a_h[mt], b_h[nt]);
                #pragma unroll
                for (int mt = 0; mt < 4; mt++)
                    #pragma unroll
                    for (int nt = 0; nt < 4; nt++)
                        mma_bf16(acc[mt][nt], a_h[mt], b_l[nt]);
                #pragma unroll
                for (int mt = 0; mt < 4; mt++)
                    #pragma unroll
                    for (int nt = 0; nt < 4; nt++)
                        mma_bf16(acc[mt][nt], a_l[mt], b_h[nt]);
            }

            if (t + 1 < T) sts_B(bnxt, tid, br);
            __syncthreads();
        }
    }

    // epilogue: D fragment m16n8 -> rows lane>>2 (+8), cols (lane&3)*2
    #pragma unroll
    for (int mt = 0; mt < 4; mt++) {
        #pragma unroll
        for (int half = 0; half < 2; half++) {
            int row = m0 + wm * 64 + mt * 16 + (lane >> 2) + 8 * half;
            int bu = row * Uu + u;
            bool sel = (mode == 1) ? (mk[bu] != 0.f) : false;
            #pragma unroll
            for (int nt = 0; nt < 4; nt++) {
                int col = n0 + wn * 32 + nt * 8 + (lane & 3) * 2;
                size_t idx = (size_t)bu * ldc + col;
                float2 v;
                v.x = acc[mt][nt][2 * half + 0];
                v.y = acc[mt][nt][2 * half + 1];
                if (mode == 1) {
                    if (sel) {
                        float2 h = *(const float2*)&ht[idx];
                        v.x += h.x; v.y += h.y;
                    } else {
                        v = *(const float2*)&hs_in[idx];
                    }
                    *(float2*)&outp[idx] = v;
                } else {
                    *(float2*)&Csel[idx] = v;
                }
            }
        }
    }
}

// ---------------- LSTM gates + cs_new + ht (f32 + bf16 hi/lo) ----------------
__global__ void gates_kernel(const float* __restrict__ cs, float* __restrict__ out_cs) {
    int idx = blockIdx.x * blockDim.x + threadIdx.x;
    if (idx >= Bsz * Uu * Hh) return;
    int h  = idx % Hh;
    int bu = idx / Hh;
    size_t base = (size_t)bu * 4 * Hh;
    float pi = g_pre[base + h];
    float pf = g_pre[base + Hh + h];
    float po = g_pre[base + 2 * Hh + h];
    float pg = g_pre[base + 3 * Hh + h];
    float it = 1.f / (1.f + expf(-pi));
    float ft = 1.f / (1.f + expf(-pf));
    float ot = 1.f / (1.f + expf(-po));
    float gt = tanhf(pg);
    float c  = cs[idx] * ft + it * gt;
    float htv = ot * tanhf(c);
    g_ht[idx] = htv;
    bf16 hh = __float2bfloat16_rn(htv);
    g_hth[idx] = hh;
    g_htl[idx] = __float2bfloat16_rn(htv - __bfloat162float(hh));
    out_cs[idx] = (g_mask[bu] != 0.f) ? c : cs[idx];
}

// ---------------- communication attention: ctx (bf16 hi/lo out) --------------
__global__ void __launch_bounds__(256) attn_kernel() {
    int b = blockIdx.x >> 2;
    int head = blockIdx.x & 3;
    __shared__ float qcs[Uu][CKk + 1], kcs[Uu][CKk + 1], att[Uu][Uu];
    int tid = threadIdx.x;
    for (int i = tid; i < Uu * CKk; i += 256) {
        int uu = i / CKk, c = i % CKk;
        size_t base = (size_t)(b * Uu + uu) * (NCHh * CKk) + head * CKk + c;
        qcs[uu][c] = g_qc[base];
        kcs[uu][c] = g_kc[base];
    }
    __syncthreads();
    for (int i = tid; i < Uu * Uu; i += 256) {
        int uu = i / Uu, t = i % Uu;
        float s = 0.f;
        #pragma unroll
        for (int c = 0; c < CKk; c++) s += qcs[uu][c] * kcs[t][c];
        att[uu][t] = s * 0.17677669529663687f;
    }
    __syncthreads();
    if (tid < Uu) {
        float m = -1e30f;
        #pragma unroll
        for (int t = 0; t < Uu; t++) m = fmaxf(m, att[tid][t]);
        float sum = 0.f;
        #pragma unroll
        for (int t = 0; t < Uu; t++) {
            float e = expf(att[tid][t] - m);
            att[tid][t] = e;
            sum += e;
        }
        float inv = 1.f / sum;
        #pragma unroll
        for (int t = 0; t < Uu; t++) att[tid][t] *= inv;
    }
    __syncthreads();
    float accx[Uu], accy[Uu];
    #pragma unroll
    for (int uu = 0; uu < Uu; uu++) { accx[uu] = 0.f; accy[uu] = 0.f; }
    int v0 = tid * 2;
    #pragma unroll 4
    for (int t = 0; t < Uu; t++) {
        float2 vv = *(const float2*)&g_vc[(size_t)(b * Uu + t) * (NCHh * CVv) + head * CVv + v0];
        #pragma unroll
        for (int uu = 0; uu < Uu; uu++) {
            float a = att[uu][t];
            accx[uu] += a * vv.x;
            accy[uu] += a * vv.y;
        }
    }
    #pragma unroll
    for (int uu = 0; uu < Uu; uu++) {
        size_t o = (size_t)(b * Uu + uu) * (NCHh * CVv) + head * CVv + v0;
        bf16 hx = __float2bfloat16_rn(accx[uu]);
        bf16 hy = __float2bfloat16_rn(accy[uu]);
        g_ctx_h[o]     = hx;
        g_ctx_h[o + 1] = hy;
        g_ctx_l[o]     = __float2bfloat16_rn(accx[uu] - __bfloat162float(hx));
        g_ctx_l[o + 1] = __float2bfloat16_rn(accy[uu] - __bfloat162float(hy));
    }
}

// ---------------- launch ----------------
extern "C" void kernel_launch(void* const* d_in, const int* in_sizes, int n_in,
                              void* d_out, int out_size) {
    const float* x       = (const float*)d_in[0];
    const float* hs      = (const float*)d_in[1];
    const float* cs      = (const float*)d_in[2];
    const float* key_w   = (const float*)d_in[3];
    const float* key_b   = (const float*)d_in[4];
    const float* value_w = (const float*)d_in[5];
    const float* value_b = (const float*)d_in[6];
    const float* query_w = (const float*)d_in[7];
    const float* i2h_w   = (const float*)d_in[8];
    const float* h2h_w   = (const float*)d_in[9];
    const float* qc_w    = (const float*)d_in[10];
    const float* kc_w    = (const float*)d_in[11];
    const float* vc_w    = (const float*)d_in[12];
    const float* co_w    = (const float*)d_in[13];
    float* out    = (float*)d_out;
    float* out_hs = out;
    float* out_cs = out + (size_t)Bsz * Uu * Hh;

    cudaFuncSetAttribute(bgemm, cudaFuncAttributeMaxDynamicSharedMemorySize, SMEMT);

    float *p_pre, *p_ht, *p_qc, *p_kc, *p_vc, *p_mask;
    cudaGetSymbolAddress((void**)&p_pre,  g_pre);
    cudaGetSymbolAddress((void**)&p_ht,   g_ht);
    cudaGetSymbolAddress((void**)&p_qc,   g_qc);
    cudaGetSymbolAddress((void**)&p_kc,   g_kc);
    cudaGetSymbolAddress((void**)&p_vc,   g_vc);
    cudaGetSymbolAddress((void**)&p_mask, g_mask);
    bf16 *p_inp_h, *p_inp_l, *p_hs_h, *p_hs_l, *p_hth, *p_htl, *p_ctx_h, *p_ctx_l;
    cudaGetSymbolAddress((void**)&p_inp_h, g_inp_h);
    cudaGetSymbolAddress((void**)&p_inp_l, g_inp_l);
    cudaGetSymbolAddress((void**)&p_hs_h,  g_hs_h);
    cudaGetSymbolAddress((void**)&p_hs_l,  g_hs_l);
    cudaGetSymbolAddress((void**)&p_hth,   g_hth);
    cudaGetSymbolAddress((void**)&p_htl,   g_htl);
    cudaGetSymbolAddress((void**)&p_ctx_h, g_ctx_h);
    cudaGetSymbolAddress((void**)&p_ctx_l, g_ctx_l);

    // --- stage A ---
    kv_kernel<<<Bsz, 512>>>(x, key_w, key_b, value_w, value_b);
    qscore_kernel<<<Bsz * Uu, 64>>>(hs, query_w, key_b);
    topk_kernel<<<1, Bsz>>>();
    inp_kernel<<<(Bsz * Uu * IVP + 255) / 256, 256>>>(value_b);
    hsconv_kernel<<<(Bsz * Uu * Hh + 255) / 256, 256>>>(hs);

    // --- preact = inp@i2h + hs@h2h (dual pass, K=416(400 real)+512) ---
    bgemm<<<dim3(2048 / 128, Bsz / 128, Uu), 256, SMEMT>>>(
        p_inp_h, p_inp_l, IVP, Uu * IVP, i2h_w, IVP, IVv,
        p_hs_h,  p_hs_l,  Hh,  Uu * Hh,  h2h_w, Hh, Hh,
        2048, p_pre, 0, nullptr, nullptr, nullptr, nullptr, nullptr);

    gates_kernel<<<(Bsz * Uu * Hh + 255) / 256, 256>>>(cs, out_cs);

    // --- qc & kc merged (N=128 each, mode 2) ---
    bgemm<<<dim3(2, Bsz / 128, Uu), 256, SMEMT>>>(
        p_hth, p_htl, Hh, Uu * Hh, qc_w, Hh, Hh,
        nullptr, nullptr, 0, 0, kc_w, 0, Hh,
        128, p_qc, 2, p_kc, nullptr, nullptr, nullptr, nullptr);

    // --- vc (N=2048) ---
    bgemm<<<dim3(2048 / 128, Bsz / 128, Uu), 256, SMEMT>>>(
        p_hth, p_htl, Hh, Uu * Hh, vc_w, Hh, Hh,
        nullptr, nullptr, 0, 0, nullptr, 0, 0,
        2048, p_vc, 0, nullptr, nullptr, nullptr, nullptr, nullptr);

    attn_kernel<<<Bsz * NCHh, 256>>>();

    // --- co GEMM with fused hs_new epilogue ---
    bgemm<<<dim3(512 / 128, Bsz / 128, Uu), 256, SMEMT>>>(
        p_ctx_h, p_ctx_l, NCHh * CVv, Uu * NCHh * CVv, co_w, NCHh * CVv, NCHh * CVv,
        nullptr, nullptr, 0, 0, nullptr, 0, 0,
        512, nullptr, 1, nullptr, p_ht, p_mask, hs, out_hs);
}

// round 14
// speedup vs baseline: 1.0033x; 1.0033x over previous
#include <cuda_runtime.h>
#include <cuda_bf16.h>
#include <math.h>
#include <stddef.h>
#include <stdint.h>

#define Bsz 256
#define Dd  512
#define Hh  512
#define Uu  24
#define Kk  8
#define IKk 64
#define IVv 400
#define IVP 416        // IVv padded to multiple of 32
#define CKk 32
#define NCHh 4
#define CVv 512

typedef __nv_bfloat16 bf16;

// ---------------- fp32 scratch ----------------
__device__ float g_k0[Bsz * IKk];
__device__ float g_v0[Bsz * IVv];
__device__ float g_s0[Bsz * Uu];
__device__ float g_p0[Bsz * Uu];
__device__ float g_mask[Bsz * Uu];
__device__ float g_pre[(size_t)Bsz * Uu * 4 * Hh];   // 50 MB
__device__ float g_ht[Bsz * Uu * Hh];
__device__ float g_qc[Bsz * Uu * NCHh * CKk];
__device__ float g_kc[Bsz * Uu * NCHh * CKk];
__device__ float g_vc[(size_t)Bsz * Uu * NCHh * CVv];  // 50 MB

// ---------------- bf16 hi/lo activations (A operands) -------------
__device__ __align__(16) bf16 g_inp_h[Bsz * Uu * IVP];
__device__ __align__(16) bf16 g_inp_l[Bsz * Uu * IVP];
__device__ __align__(16) bf16 g_hs_h[Bsz * Uu * Hh];
__device__ __align__(16) bf16 g_hs_l[Bsz * Uu * Hh];
__device__ __align__(16) bf16 g_hth[Bsz * Uu * Hh];
__device__ __align__(16) bf16 g_htl[Bsz * Uu * Hh];
__device__ __align__(16) bf16 g_ctx_h[(size_t)Bsz * Uu * NCHh * CVv];
__device__ __align__(16) bf16 g_ctx_l[(size_t)Bsz * Uu * NCHh * CVv];

// ===================== PTX helpers (baseline sm_80+ only) =====================
__device__ __forceinline__ uint32_t smem_u32(const void* p) {
    uint32_t a;
    asm("{ .reg .u64 t; cvta.to.shared.u64 t, %1; cvt.u32.u64 %0, t; }" : "=r"(a) : "l"(p));
    return a;
}
__device__ __forceinline__ void cp16(uint32_t dst, const void* src) {
    asm volatile("cp.async.cg.shared.global [%0], [%1], 16;"
                 :: "r"(dst), "l"(__cvta_generic_to_global(src)) : "memory");
}
__device__ __forceinline__ void cp_commit() {
    asm volatile("cp.async.commit_group;" ::: "memory");
}
__device__ __forceinline__ void cp_wait0() {
    asm volatile("cp.async.wait_group 0;" ::: "memory");
}
__device__ __forceinline__ void cp_wait1() {
    asm volatile("cp.async.wait_group 1;" ::: "memory");
}
__device__ __forceinline__ void ldsm_x4(uint32_t* r, uint32_t addr) {
    asm volatile("ldmatrix.sync.aligned.m8n8.x4.shared.b16 {%0,%1,%2,%3}, [%4];"
                 : "=r"(r[0]), "=r"(r[1]), "=r"(r[2]), "=r"(r[3]) : "r"(addr));
}
__device__ __forceinline__ void ldsm_x2_trans(uint32_t* r, uint32_t addr) {
    asm volatile("ldmatrix.sync.aligned.m8n8.x2.trans.shared.b16 {%0,%1}, [%2];"
                 : "=r"(r[0]), "=r"(r[1]) : "r"(addr));
}
__device__ __forceinline__ void mma_bf16(float* d, const uint32_t* a, const uint32_t* b) {
    asm volatile(
        "mma.sync.aligned.m16n8k16.row.col.f32.bf16.bf16.f32 "
        "{%0,%1,%2,%3}, {%4,%5,%6,%7}, {%8,%9}, {%0,%1,%2,%3};"
        : "+f"(d[0]), "+f"(d[1]), "+f"(d[2]), "+f"(d[3])
        : "r"(a[0]), "r"(a[1]), "r"(a[2]), "r"(a[3]), "r"(b[0]), "r"(b[1]));
}

// ---------------- stage A: k0 = x@key_w+key_b, v0 = x@value_w+value_b ------
__global__ void kv_kernel(const float* __restrict__ x,
                          const float* __restrict__ key_w, const float* __restrict__ key_b,
                          const float* __restrict__ value_w, const float* __restrict__ value_b) {
    int b = blockIdx.x;
    __shared__ float xs[Dd];
    int tid = threadIdx.x; // 512
    xs[tid] = x[(size_t)b * Dd + tid];
    __syncthreads();
    if (tid < IVv) {
        float acc = value_b[tid];
        #pragma unroll 8
        for (int d = 0; d < Dd; d++) acc += xs[d] * value_w[(size_t)d * IVv + tid];
        g_v0[b * IVv + tid] = acc;
    } else if (tid < IVv + IKk) {
        int ik = tid - IVv;
        float acc = key_b[ik];
        #pragma unroll 8
        for (int d = 0; d < Dd; d++) acc += xs[d] * key_w[(size_t)d * IKk + ik];
        g_k0[b * IKk + ik] = acc;
    }
}

// ---------------- stage A: q, scores, probs ----------------
__global__ void qscore_kernel(const float* __restrict__ hs,
                              const float* __restrict__ query_w,
                              const float* __restrict__ key_b) {
    int bu = blockIdx.x;
    int b = bu / Uu, u = bu % Uu;
    int ik = threadIdx.x; // 64
    __shared__ float hss[Hh];
    for (int i = ik; i < Hh; i += 64) hss[i] = hs[(size_t)bu * Hh + i];
    __syncthreads();
    const float* qw = query_w + (size_t)u * Hh * IKk;
    float q = 0.f;
    #pragma unroll 8
    for (int d = 0; d < Hh; d++) q += hss[d] * qw[(size_t)d * IKk + ik];
    float p0 = q * g_k0[b * IKk + ik];
    float p1 = q * key_b[ik];
    #pragma unroll
    for (int off = 16; off > 0; off >>= 1) {
        p0 += __shfl_down_sync(0xffffffffu, p0, off);
        p1 += __shfl_down_sync(0xffffffffu, p1, off);
    }
    __shared__ float r0[2], r1[2];
    if ((ik & 31) == 0) { r0[ik >> 5] = p0; r1[ik >> 5] = p1; }
    __syncthreads();
    if (ik == 0) {
        float s0 = (r0[0] + r0[1]) * 0.125f;
        float s1 = (r1[0] + r1[1]) * 0.125f;
        g_s0[bu] = s0;
        float m = fmaxf(s0, s1);
        float e0 = expf(s0 - m), e1 = expf(s1 - m);
        g_p0[bu] = e0 / (e0 + e1);
    }
}

// ---------------- top-k mask ----------------
__global__ void topk_kernel() {
    int b = threadIdx.x;
    float s[Uu];
    #pragma unroll
    for (int u = 0; u < Uu; u++) s[u] = g_s0[b * Uu + u];
    #pragma unroll
    for (int u = 0; u < Uu; u++) {
        int cnt = 0;
        #pragma unroll
        for (int t = 0; t < Uu; t++)
            if (s[t] > s[u] || (s[t] == s[u] && t < u)) cnt++;
        g_mask[b * Uu + u] = (cnt < Kk) ? 1.f : 0.f;
    }
}

// ---------------- inp (bf16 hi/lo out, padded K to 416) ----------------
__global__ void inp_kernel(const float* __restrict__ value_b) {
    int idx = blockIdx.x * blockDim.x + threadIdx.x;
    if (idx >= Bsz * Uu * IVP) return;
    int iv = idx % IVP;
    int bu = idx / IVP;
    int b = bu / Uu;
    float v = 0.f;
    if (iv < IVv) {
        float p0 = g_p0[bu];
        v = p0 * g_v0[b * IVv + iv] + (1.f - p0) * value_b[iv];
        v *= g_mask[bu];
    }
    bf16 h = __float2bfloat16_rn(v);
    g_inp_h[idx] = h;
    g_inp_l[idx] = __float2bfloat16_rn(v - __bfloat162float(h));
}

// ---------------- hs -> bf16 hi/lo ----------------
__global__ void hsconv_kernel(const float* __restrict__ hs) {
    int idx = blockIdx.x * blockDim.x + threadIdx.x;
    if (idx >= Bsz * Uu * Hh) return;
    float v = hs[idx];
    bf16 h = __float2bfloat16_rn(v);
    g_hs_h[idx] = h;
    g_hs_l[idx] = __float2bfloat16_rn(v - __bfloat162float(h));
}

// ===================== bf16-split tensor-core GEMM (mma.sync) =====================
// D[(b*U+u)*ldc + n] = sum_k A(b,u,k) * W[u][k][n], hi/lo split, fp32 acc.
// Weights consumed DIRECTLY as f32 [u][K][N]: LDG.128 prefetch -> in-register
// hi/lo bf16 split -> STS into padded row-major tiles -> ldmatrix.trans.
// CTA 128x128, 8 warps (2Mx4N), BK=32, A via cp.async (bf16 hi/lo activations).
// mode 0: store C. mode 1: out = mask ? acc+ht : hs_in. mode 2: blockIdx.x picks
//         (Bw1,C) vs (Bw2,C2), n0=0, single pass.
#define BKc   32
#define BKp   40
#define BNp   136
#define AST   (128 * BKp * 2)     // 10240 B per A tile
#define BST   (BKc * BNp * 2)     // 8704 B per B tile
#define STAGE (2 * AST + 2 * BST) // 37888 B
#define SMEMT (2 * STAGE)         // 75776 B

extern __shared__ char gsm[];

struct GArgs {
    const bf16 *Auh, *Aul;
    const float *Bw;          // native f32 weights, offset by u and n0
    int K, Kreal, ars, ldw;
};

__device__ __forceinline__ void issue_A(const GArgs& ga, uint32_t sbuf,
                                        int k0, int tid) {
    #pragma unroll
    for (int h = 0; h < 2; h++) {
        int c = tid + h * 256;
        int arow = c >> 2, aseg = c & 3;
        uint32_t ad = sbuf + (uint32_t)(arow * (BKp * 2) + aseg * 16);
        cp16(ad,       ga.Auh + (size_t)arow * ga.ars + k0 + aseg * 8);
        cp16(ad + AST, ga.Aul + (size_t)arow * ga.ars + k0 + aseg * 8);
    }
    cp_commit();
}

// LDG prefetch of one 32x128 f32 B tile (16 f32/thread)
__device__ __forceinline__ void ldg_B(const GArgs& ga, int k0, int tid, float4* br) {
    #pragma unroll
    for (int h = 0; h < 4; h++) {
        int c = tid + h * 256;
        int row = c >> 5, seg = c & 31;
        if (k0 + row < ga.Kreal)
            br[h] = *(const float4*)(ga.Bw + (size_t)(k0 + row) * ga.ldw + seg * 4);
        else
            br[h] = make_float4(0.f, 0.f, 0.f, 0.f);
    }
}

// convert + store the prefetched tile into smem hi/lo B tiles
__device__ __forceinline__ void sts_B(char* bufB, int tid, const float4* br) {
    #pragma unroll
    for (int h = 0; h < 4; h++) {
        int c = tid + h * 256;
        int row = c >> 5, seg = c & 31;
        float4 v = br[h];
        bf16 h0 = __float2bfloat16_rn(v.x), h1 = __float2bfloat16_rn(v.y);
        bf16 h2 = __float2bfloat16_rn(v.z), h3 = __float2bfloat16_rn(v.w);
        bf16 l0 = __float2bfloat16_rn(v.x - __bfloat162float(h0));
        bf16 l1 = __float2bfloat16_rn(v.y - __bfloat162float(h1));
        bf16 l2 = __float2bfloat16_rn(v.z - __bfloat162float(h2));
        bf16 l3 = __float2bfloat16_rn(v.w - __bfloat162float(h3));
        uint2 ph, pl;
        ph.x = (uint32_t)__bfloat16_as_ushort(h0) | ((uint32_t)__bfloat16_as_ushort(h1) << 16);
        ph.y = (uint32_t)__bfloat16_as_ushort(h2) | ((uint32_t)__bfloat16_as_ushort(h3) << 16);
        pl.x = (uint32_t)__bfloat16_as_ushort(l0) | ((uint32_t)__bfloat16_as_ushort(l1) << 16);
        pl.y = (uint32_t)__bfloat16_as_ushort(l2) | ((uint32_t)__bfloat16_as_ushort(l3) << 16);
        char* p = bufB + row * (BNp * 2) + seg * 8;
        *(uint2*)p         = ph;
        *(uint2*)(p + BST) = pl;
    }
}

__global__ void __launch_bounds__(256) bgemm(
    const bf16* __restrict__ Ah1, const bf16* __restrict__ Al1, int a1_uoff, int a1_rs,
    const float* __restrict__ Bw1, int K1, int K1real,
    const bf16* __restrict__ Ah2, const bf16* __restrict__ Al2, int a2_uoff, int a2_rs,
    const float* __restrict__ Bw2, int K2, int K2real,
    int ldc, float* __restrict__ C, int mode, float* __restrict__ C2,
    const float* __restrict__ ht, const float* __restrict__ mk,
    const float* __restrict__ hs_in, float* __restrict__ outp)
{
    uint32_t sb = smem_u32(gsm);
    int tid  = threadIdx.x;
    int lane = tid & 31, wid = tid >> 5;
    int wm = wid & 1, wn = wid >> 1;
    int u = blockIdx.z, m0 = blockIdx.y * 128;
    int n0;
    const float* Bw = Bw1;
    float* Csel = C;
    if (mode == 2) {
        n0 = 0;
        if (blockIdx.x) { Bw = Bw2; Csel = C2; }
    } else {
        n0 = blockIdx.x * 128;
    }

    float acc[4][4][4];
    #pragma unroll
    for (int i = 0; i < 4; i++)
        #pragma unroll
        for (int j = 0; j < 4; j++)
            #pragma unroll
            for (int k = 0; k < 4; k++) acc[i][j][k] = 0.f;

    int a_ro = lane & 15, a_cg = lane >> 4;
    int b_kr = (lane & 7) + 8 * ((lane >> 3) & 1);

    int npass = (mode != 2 && K2 > 0) ? 2 : 1;
    #pragma unroll 1
    for (int pass = 0; pass < npass; pass++) {
        GArgs ga;
        if (pass == 0) {
            ga.Auh = Ah1 + (size_t)u * a1_uoff + (size_t)m0 * a1_rs;
            ga.Aul = Al1 + (size_t)u * a1_uoff + (size_t)m0 * a1_rs;
            ga.Bw  = Bw + (size_t)u * K1real * ldc + n0;
            ga.K = K1; ga.Kreal = K1real; ga.ars = a1_rs; ga.ldw = ldc;
        } else {
            ga.Auh = Ah2 + (size_t)u * a2_uoff + (size_t)m0 * a2_rs;
            ga.Aul = Al2 + (size_t)u * a2_uoff + (size_t)m0 * a2_rs;
            ga.Bw  = Bw2 + (size_t)u * K2real * ldc + n0;
            ga.K = K2; ga.Kreal = K2real; ga.ars = a2_rs; ga.ldw = ldc;
        }
        int T = ga.K / BKc;

        float4 br[4];
        // prologue: tile 0
        ldg_B(ga, 0, tid, br);
        issue_A(ga, sb, 0, tid);
        sts_B(gsm + 2 * AST, tid, br);

        #pragma unroll 1
        for (int t = 0; t < T; t++) {
            uint32_t scur = sb + (uint32_t)((t & 1) * STAGE);
            char* bnxt = gsm + ((t + 1) & 1) * STAGE + 2 * AST;
            if (t + 1 < T) {
                ldg_B(ga, (t + 1) * BKc, tid, br);
                issue_A(ga, sb + (uint32_t)(((t + 1) & 1) * STAGE), (t + 1) * BKc, tid);
                cp_wait1();
            } else {
                cp_wait0();
            }
            __syncthreads();   // current stage (A cp.async + B STS) ready

            #pragma unroll
            for (int ks = 0; ks < 2; ks++) {
                int koff = ks * 16;
                uint32_t a_h[4][4], a_l[4][4], b_h[4][2], b_l[4][2];
                #pragma unroll
                for (int mt = 0; mt < 4; mt++) {
                    uint32_t ad = scur +
                        (uint32_t)(((wm * 64 + mt * 16 + a_ro) * BKp + koff + a_cg * 8) * 2);
                    ldsm_x4(a_h[mt], ad);
                    ldsm_x4(a_l[mt], ad + AST);
                }
                #pragma unroll
                for (int nt = 0; nt < 4; nt++) {
                    uint32_t bd = scur + 2 * AST +
                        (uint32_t)(((koff + b_kr) * BNp + wn * 32 + nt * 8) * 2);
                    ldsm_x2_trans(b_h[nt], bd);
                    ldsm_x2_trans(b_l[nt], bd + BST);
                }
                #pragma unroll
                for (int mt = 0; mt < 4; mt++)
                    #pragma unroll
                    for (int nt = 0; nt < 4; nt++)
                        mma_bf16(acc[mt][nt], a_h[mt], b_h[nt]);
                #pragma unroll
                for (int mt = 0; mt < 4; mt++)
                    #pragma unroll
                    for (int nt = 0; nt < 4; nt++)
                        mma_bf16(acc[mt][nt], a_h[mt], b_l[nt]);
                #pragma unroll
                for (int mt = 0; mt < 4; mt++)
                    #pragma unroll
                    for (int nt = 0; nt < 4; nt++)
                        mma_bf16(acc[mt][nt], a_l[mt], b_h[nt]);
            }

            if (t + 1 < T) sts_B(bnxt, tid, br);
            __syncthreads();
        }
    }

    // epilogue: D fragment m16n8 -> rows lane>>2 (+8), cols (lane&3)*2
    #pragma unroll
    for (int mt = 0; mt < 4; mt++) {
        #pragma unroll
        for (int half = 0; half < 2; half++) {
            int row = m0 + wm * 64 + mt * 16 + (lane >> 2) + 8 * half;
            int bu = row * Uu + u;
            bool sel = (mode == 1) ? (mk[bu] != 0.f) : false;
            #pragma unroll
            for (int nt = 0; nt < 4; nt++) {
                int col = n0 + wn * 32 + nt * 8 + (lane & 3) * 2;
                size_t idx = (size_t)bu * ldc + col;
                float2 v;
                v.x = acc[mt][nt][2 * half + 0];
                v.y = acc[mt][nt][2 * half + 1];
                if (mode == 1) {
                    if (sel) {
                        float2 h = *(const float2*)&ht[idx];
                        v.x += h.x; v.y += h.y;
                    } else {
                        v = *(const float2*)&hs_in[idx];
                    }
                    *(float2*)&outp[idx] = v;
                } else {
                    *(float2*)&Csel[idx] = v;
                }
            }
        }
    }
}

// ---------------- LSTM gates + cs_new + ht (f32 + bf16 hi/lo) ----------------
__global__ void gates_kernel(const float* __restrict__ cs, float* __restrict__ out_cs) {
    int idx = blockIdx.x * blockDim.x + threadIdx.x;
    if (idx >= Bsz * Uu * Hh) return;
    int h  = idx % Hh;
    int bu = idx / Hh;
    size_t base = (size_t)bu * 4 * Hh;
    float pi = g_pre[base + h];
    float pf = g_pre[base + Hh + h];
    float po = g_pre[base + 2 * Hh + h];
    float pg = g_pre[base + 3 * Hh + h];
    float it = 1.f / (1.f + expf(-pi));
    float ft = 1.f / (1.f + expf(-pf));
    float ot = 1.f / (1.f + expf(-po));
    float gt = tanhf(pg);
    float c  = cs[idx] * ft + it * gt;
    float htv = ot * tanhf(c);
    g_ht[idx] = htv;
    bf16 hh = __float2bfloat16_rn(htv);
    g_hth[idx] = hh;
    g_htl[idx] = __float2bfloat16_rn(htv - __bfloat162float(hh));
    out_cs[idx] = (g_mask[bu] != 0.f) ? c : cs[idx];
}

// ---------------- communication attention: ctx (bf16 hi/lo out) --------------
__global__ void __launch_bounds__(256) attn_kernel() {
    int b = blockIdx.x >> 2;
    int head = blockIdx.x & 3;
    __shared__ float qcs[Uu][CKk + 1], kcs[Uu][CKk + 1], att[Uu][Uu];
    int tid = threadIdx.x;
    for (int i = tid; i < Uu * CKk; i += 256) {
        int uu = i / CKk, c = i % CKk;
        size_t base = (size_t)(b * Uu + uu) * (NCHh * CKk) + head * CKk + c;
        qcs[uu][c] = g_qc[base];
        kcs[uu][c] = g_kc[base];
    }
    __syncthreads();
    for (int i = tid; i < Uu * Uu; i += 256) {
        int uu = i / Uu, t = i % Uu;
        float s = 0.f;
        #pragma unroll
        for (int c = 0; c < CKk; c++) s += qcs[uu][c] * kcs[t][c];
        att[uu][t] = s * 0.17677669529663687f;
    }
    __syncthreads();
    if (tid < Uu) {
        float m = -1e30f;
        #pragma unroll
        for (int t = 0; t < Uu; t++) m = fmaxf(m, att[tid][t]);
        float sum = 0.f;
        #pragma unroll
        for (int t = 0; t < Uu; t++) {
            float e = expf(att[tid][t] - m);
            att[tid][t] = e;
            sum += e;
        }
        float inv = 1.f / sum;
        #pragma unroll
        for (int t = 0; t < Uu; t++) att[tid][t] *= inv;
    }
    __syncthreads();
    float accx[Uu], accy[Uu];
    #pragma unroll
    for (int uu = 0; uu < Uu; uu++) { accx[uu] = 0.f; accy[uu] = 0.f; }
    int v0 = tid * 2;
    #pragma unroll 4
    for (int t = 0; t < Uu; t++) {
        float2 vv = *(const float2*)&g_vc[(size_t)(b * Uu + t) * (NCHh * CVv) + head * CVv + v0];
        #pragma unroll
        for (int uu = 0; uu < Uu; uu++) {
            float a = att[uu][t];
            accx[uu] += a * vv.x;
            accy[uu] += a * vv.y;
        }
    }
    #pragma unroll
    for (int uu = 0; uu < Uu; uu++) {
        size_t o = (size_t)(b * Uu + uu) * (NCHh * CVv) + head * CVv + v0;
        bf16 hx = __float2bfloat16_rn(accx[uu]);
        bf16 hy = __float2bfloat16_rn(accy[uu]);
        g_ctx_h[o]     = hx;
        g_ctx_h[o + 1] = hy;
        g_ctx_l[o]     = __float2bfloat16_rn(accx[uu] - __bfloat162float(hx));
        g_ctx_l[o + 1] = __float2bfloat16_rn(accy[uu] - __bfloat162float(hy));
    }
}

// ---------------- launch ----------------
extern "C" void kernel_launch(void* const* d_in, const int* in_sizes, int n_in,
                              void* d_out, int out_size) {
    const float* x       = (const float*)d_in[0];
    const float* hs      = (const float*)d_in[1];
    const float* cs      = (const float*)d_in[2];
    const float* key_w   = (const float*)d_in[3];
    const float* key_b   = (const float*)d_in[4];
    const float* value_w = (const float*)d_in[5];
    const float* value_b = (const float*)d_in[6];
    const float* query_w = (const float*)d_in[7];
    const float* i2h_w   = (const float*)d_in[8];
    const float* h2h_w   = (const float*)d_in[9];
    const float* qc_w    = (const float*)d_in[10];
    const float* kc_w    = (const float*)d_in[11];
    const float* vc_w    = (const float*)d_in[12];
    const float* co_w    = (const float*)d_in[13];
    float* out    = (float*)d_out;
    float* out_hs = out;
    float* out_cs = out + (size_t)Bsz * Uu * Hh;

    cudaFuncSetAttribute(bgemm, cudaFuncAttributeMaxDynamicSharedMemorySize, SMEMT);

    float *p_pre, *p_ht, *p_qc, *p_kc, *p_vc, *p_mask;
    cudaGetSymbolAddress((void**)&p_pre,  g_pre);
    cudaGetSymbolAddress((void**)&p_ht,   g_ht);
    cudaGetSymbolAddress((void**)&p_qc,   g_qc);
    cudaGetSymbolAddress((void**)&p_kc,   g_kc);
    cudaGetSymbolAddress((void**)&p_vc,   g_vc);
    cudaGetSymbolAddress((void**)&p_mask, g_mask);
    bf16 *p_inp_h, *p_inp_l, *p_hs_h, *p_hs_l, *p_hth, *p_htl, *p_ctx_h, *p_ctx_l;
    cudaGetSymbolAddress((void**)&p_inp_h, g_inp_h);
    cudaGetSymbolAddress((void**)&p_inp_l, g_inp_l);
    cudaGetSymbolAddress((void**)&p_hs_h,  g_hs_h);
    cudaGetSymbolAddress((void**)&p_hs_l,  g_hs_l);
    cudaGetSymbolAddress((void**)&p_hth,   g_hth);
    cudaGetSymbolAddress((void**)&p_htl,   g_htl);
    cudaGetSymbolAddress((void**)&p_ctx_h, g_ctx_h);
    cudaGetSymbolAddress((void**)&p_ctx_l, g_ctx_l);

    // --- stage A ---
    kv_kernel<<<Bsz, 512>>>(x, key_w, key_b, value_w, value_b);
    qscore_kernel<<<Bsz * Uu, 64>>>(hs, query_w, key_b);
    topk_kernel<<<1, Bsz>>>();
    inp_kernel<<<(Bsz * Uu * IVP + 255) / 256, 256>>>(value_b);
    hsconv_kernel<<<(Bsz * Uu * Hh + 255) / 256, 256>>>(hs);

    // --- preact = inp@i2h + hs@h2h (dual pass, K=416(400 real)+512) ---
    bgemm<<<dim3(2048 / 128, Bsz / 128, Uu), 256, SMEMT>>>(
        p_inp_h, p_inp_l, IVP, Uu * IVP, i2h_w, IVP, IVv,
        p_hs_h,  p_hs_l,  Hh,  Uu * Hh,  h2h_w, Hh, Hh,
        2048, p_pre, 0, nullptr, nullptr, nullptr, nullptr, nullptr);

    gates_kernel<<<(Bsz * Uu * Hh + 255) / 256, 256>>>(cs, out_cs);

    // --- qc & kc merged (N=128 each, mode 2) ---
    bgemm<<<dim3(2, Bsz / 128, Uu), 256, SMEMT>>>(
        p_hth, p_htl, Hh, Uu * Hh, qc_w, Hh, Hh,
        nullptr, nullptr, 0, 0, kc_w, 0, Hh,
        128, p_qc, 2, p_kc, nullptr, nullptr, nullptr, nullptr);

    // --- vc (N=2048) ---
    bgemm<<<dim3(2048 / 128, Bsz / 128, Uu), 256, SMEMT>>>(
        p_hth, p_htl, Hh, Uu * Hh, vc_w, Hh, Hh,
        nullptr, nullptr, 0, 0, nullptr, 0, 0,
        2048, p_vc, 0, nullptr, nullptr, nullptr, nullptr, nullptr);

    attn_kernel<<<Bsz * NCHh, 256>>>();

    // --- co GEMM with fused hs_new epilogue ---
    bgemm<<<dim3(512 / 128, Bsz / 128, Uu), 256, SMEMT>>>(
        p_ctx_h, p_ctx_l, NCHh * CVv, Uu * NCHh * CVv, co_w, NCHh * CVv, NCHh * CVv,
        nullptr, nullptr, 0, 0, nullptr, 0, 0,
        512, nullptr, 1, nullptr, p_ht, p_mask, hs, out_hs);
}

// round 15
// speedup vs baseline: 1.0920x; 1.0884x over previous
#include <cuda_runtime.h>
#include <cuda_bf16.h>
#include <math.h>
#include <stddef.h>
#include <stdint.h>

#define Bsz 256
#define Dd  512
#define Hh  512
#define Uu  24
#define Kk  8
#define IKk 64
#define IVv 400
#define IVP 416        // IVv padded to multiple of 32
#define CKk 32
#define NCHh 4
#define CVv 512

typedef __nv_bfloat16 bf16;

// ---------------- fp32 scratch ----------------
__device__ float g_k0[Bsz * IKk];
__device__ float g_v0[Bsz * IVv];
__device__ float g_s0[Bsz * Uu];
__device__ float g_p0[Bsz * Uu];
__device__ float g_mask[Bsz * Uu];
__device__ float g_pre[(size_t)Bsz * Uu * 4 * Hh];   // 50 MB
__device__ float g_ht[Bsz * Uu * Hh];
__device__ float g_qc[Bsz * Uu * NCHh * CKk];
__device__ float g_kc[Bsz * Uu * NCHh * CKk];
__device__ float g_vc[(size_t)Bsz * Uu * NCHh * CVv];  // 50 MB

// ---------------- bf16 hi/lo activations (A operands) -------------
__device__ __align__(16) bf16 g_inp_h[Bsz * Uu * IVP];
__device__ __align__(16) bf16 g_inp_l[Bsz * Uu * IVP];
__device__ __align__(16) bf16 g_hs_h[Bsz * Uu * Hh];
__device__ __align__(16) bf16 g_hs_l[Bsz * Uu * Hh];
__device__ __align__(16) bf16 g_hth[Bsz * Uu * Hh];
__device__ __align__(16) bf16 g_htl[Bsz * Uu * Hh];
__device__ __align__(16) bf16 g_ctx_h[(size_t)Bsz * Uu * NCHh * CVv];
__device__ __align__(16) bf16 g_ctx_l[(size_t)Bsz * Uu * NCHh * CVv];

// ---------------- bf16 hi/lo weights, NATIVE [u][Kp][N] layout ---------
#define I2H_SZ ((size_t)24 * IVP * 2048)
#define H2H_SZ ((size_t)24 * 512 * 2048)
#define QCW_SZ ((size_t)24 * 512 * 128)
#define VCW_SZ ((size_t)24 * 512 * 2048)
#define COW_SZ ((size_t)24 * 2048 * 512)
__device__ __align__(16) bf16 g_i2h_h[I2H_SZ]; __device__ __align__(16) bf16 g_i2h_l[I2H_SZ];
__device__ __align__(16) bf16 g_h2h_h[H2H_SZ]; __device__ __align__(16) bf16 g_h2h_l[H2H_SZ];
__device__ __align__(16) bf16 g_qcw_h[QCW_SZ]; __device__ __align__(16) bf16 g_qcw_l[QCW_SZ];
__device__ __align__(16) bf16 g_kcw_h[QCW_SZ]; __device__ __align__(16) bf16 g_kcw_l[QCW_SZ];
__device__ __align__(16) bf16 g_vcw_h[VCW_SZ]; __device__ __align__(16) bf16 g_vcw_l[VCW_SZ];
__device__ __align__(16) bf16 g_cow_h[COW_SZ]; __device__ __align__(16) bf16 g_cow_l[COW_SZ];

// ===================== PTX helpers (baseline sm_80+ only) =====================
__device__ __forceinline__ uint32_t smem_u32(const void* p) {
    uint32_t a;
    asm("{ .reg .u64 t; cvta.to.shared.u64 t, %1; cvt.u32.u64 %0, t; }" : "=r"(a) : "l"(p));
    return a;
}
__device__ __forceinline__ void cp16(uint32_t dst, const void* src) {
    asm volatile("cp.async.cg.shared.global [%0], [%1], 16;"
                 :: "r"(dst), "l"(__cvta_generic_to_global(src)) : "memory");
}
__device__ __forceinline__ void cp_commit() {
    asm volatile("cp.async.commit_group;" ::: "memory");
}
__device__ __forceinline__ void cp_wait0() {
    asm volatile("cp.async.wait_group 0;" ::: "memory");
}
__device__ __forceinline__ void cp_wait1() {
    asm volatile("cp.async.wait_group 1;" ::: "memory");
}
__device__ __forceinline__ void ldsm_x4(uint32_t* r, uint32_t addr) {
    asm volatile("ldmatrix.sync.aligned.m8n8.x4.shared.b16 {%0,%1,%2,%3}, [%4];"
                 : "=r"(r[0]), "=r"(r[1]), "=r"(r[2]), "=r"(r[3]) : "r"(addr));
}
__device__ __forceinline__ void ldsm_x2_trans(uint32_t* r, uint32_t addr) {
    asm volatile("ldmatrix.sync.aligned.m8n8.x2.trans.shared.b16 {%0,%1}, [%2];"
                 : "=r"(r[0]), "=r"(r[1]) : "r"(addr));
}
__device__ __forceinline__ void mma_bf16(float* d, const uint32_t* a, const uint32_t* b) {
    asm volatile(
        "mma.sync.aligned.m16n8k16.row.col.f32.bf16.bf16.f32 "
        "{%0,%1,%2,%3}, {%4,%5,%6,%7}, {%8,%9}, {%0,%1,%2,%3};"
        : "+f"(d[0]), "+f"(d[1]), "+f"(d[2]), "+f"(d[3])
        : "r"(a[0]), "r"(a[1]), "r"(a[2]), "r"(a[3]), "r"(b[0]), "r"(b[1]));
}

// ---------------- stage A: k0 = x@key_w+key_b, v0 = x@value_w+value_b ------
__global__ void kv_kernel(const float* __restrict__ x,
                          const float* __restrict__ key_w, const float* __restrict__ key_b,
                          const float* __restrict__ value_w, const float* __restrict__ value_b) {
    int b = blockIdx.x;
    __shared__ float xs[Dd];
    int tid = threadIdx.x; // 512
    xs[tid] = x[(size_t)b * Dd + tid];
    __syncthreads();
    if (tid < IVv) {
        float acc = value_b[tid];
        #pragma unroll 8
        for (int d = 0; d < Dd; d++) acc += xs[d] * value_w[(size_t)d * IVv + tid];
        g_v0[b * IVv + tid] = acc;
    } else if (tid < IVv + IKk) {
        int ik = tid - IVv;
        float acc = key_b[ik];
        #pragma unroll 8
        for (int d = 0; d < Dd; d++) acc += xs[d] * key_w[(size_t)d * IKk + ik];
        g_k0[b * IKk + ik] = acc;
    }
}

// ---------------- stage A: q, scores, probs ----------------
__global__ void qscore_kernel(const float* __restrict__ hs,
                              const float* __restrict__ query_w,
                              const float* __restrict__ key_b) {
    int bu = blockIdx.x;
    int b = bu / Uu, u = bu % Uu;
    int ik = threadIdx.x; // 64
    __shared__ float hss[Hh];
    for (int i = ik; i < Hh; i += 64) hss[i] = hs[(size_t)bu * Hh + i];
    __syncthreads();
    const float* qw = query_w + (size_t)u * Hh * IKk;
    float q = 0.f;
    #pragma unroll 8
    for (int d = 0; d < Hh; d++) q += hss[d] * qw[(size_t)d * IKk + ik];
    float p0 = q * g_k0[b * IKk + ik];
    float p1 = q * key_b[ik];
    #pragma unroll
    for (int off = 16; off > 0; off >>= 1) {
        p0 += __shfl_down_sync(0xffffffffu, p0, off);
        p1 += __shfl_down_sync(0xffffffffu, p1, off);
    }
    __shared__ float r0[2], r1[2];
    if ((ik & 31) == 0) { r0[ik >> 5] = p0; r1[ik >> 5] = p1; }
    __syncthreads();
    if (ik == 0) {
        float s0 = (r0[0] + r0[1]) * 0.125f;
        float s1 = (r1[0] + r1[1]) * 0.125f;
        g_s0[bu] = s0;
        float m = fmaxf(s0, s1);
        float e0 = expf(s0 - m), e1 = expf(s1 - m);
        g_p0[bu] = e0 / (e0 + e1);
    }
}

// ---------------- top-k mask ----------------
__global__ void topk_kernel() {
    int b = threadIdx.x;
    float s[Uu];
    #pragma unroll
    for (int u = 0; u < Uu; u++) s[u] = g_s0[b * Uu + u];
    #pragma unroll
    for (int u = 0; u < Uu; u++) {
        int cnt = 0;
        #pragma unroll
        for (int t = 0; t < Uu; t++)
            if (s[t] > s[u] || (s[t] == s[u] && t < u)) cnt++;
        g_mask[b * Uu + u] = (cnt < Kk) ? 1.f : 0.f;
    }
}

// ---------------- inp (bf16 hi/lo out, padded K to 416) ----------------
__global__ void inp_kernel(const float* __restrict__ value_b) {
    int idx = blockIdx.x * blockDim.x + threadIdx.x;
    if (idx >= Bsz * Uu * IVP) return;
    int iv = idx % IVP;
    int bu = idx / IVP;
    int b = bu / Uu;
    float v = 0.f;
    if (iv < IVv) {
        float p0 = g_p0[bu];
        v = p0 * g_v0[b * IVv + iv] + (1.f - p0) * value_b[iv];
        v *= g_mask[bu];
    }
    bf16 h = __float2bfloat16_rn(v);
    g_inp_h[idx] = h;
    g_inp_l[idx] = __float2bfloat16_rn(v - __bfloat162float(h));
}

// ---------------- hs -> bf16 hi/lo ----------------
__global__ void hsconv_kernel(const float* __restrict__ hs) {
    int idx = blockIdx.x * blockDim.x + threadIdx.x;
    if (idx >= Bsz * Uu * Hh) return;
    float v = hs[idx];
    bf16 h = __float2bfloat16_rn(v);
    g_hs_h[idx] = h;
    g_hs_l[idx] = __float2bfloat16_rn(v - __bfloat162float(h));
}

// ---------------- fast streaming weight split ----------------
__device__ __forceinline__ void split4(float4 v, uint2& ph, uint2& pl) {
    bf16 h0 = __float2bfloat16_rn(v.x), h1 = __float2bfloat16_rn(v.y);
    bf16 h2 = __float2bfloat16_rn(v.z), h3 = __float2bfloat16_rn(v.w);
    bf16 l0 = __float2bfloat16_rn(v.x - __bfloat162float(h0));
    bf16 l1 = __float2bfloat16_rn(v.y - __bfloat162float(h1));
    bf16 l2 = __float2bfloat16_rn(v.z - __bfloat162float(h2));
    bf16 l3 = __float2bfloat16_rn(v.w - __bfloat162float(h3));
    ph.x = (uint32_t)__bfloat16_as_ushort(h0) | ((uint32_t)__bfloat16_as_ushort(h1) << 16);
    ph.y = (uint32_t)__bfloat16_as_ushort(h2) | ((uint32_t)__bfloat16_as_ushort(h3) << 16);
    pl.x = (uint32_t)__bfloat16_as_ushort(l0) | ((uint32_t)__bfloat16_as_ushort(l1) << 16);
    pl.y = (uint32_t)__bfloat16_as_ushort(l2) | ((uint32_t)__bfloat16_as_ushort(l3) << 16);
}

// unpadded tensors: pure flat stream, 8 f32 -> 16B hi + 16B lo per thread
__global__ void wsplit_stream(const float4* __restrict__ W, uint4* __restrict__ Wh,
                              uint4* __restrict__ Wl, int n8) {
    int i = blockIdx.x * blockDim.x + threadIdx.x;
    if (i >= n8) return;
    float4 a = W[2 * i], b = W[2 * i + 1];
    uint2 ha, la, hb, lb;
    split4(a, ha, la);
    split4(b, hb, lb);
    uint4 ph, pl;
    ph.x = ha.x; ph.y = ha.y; ph.z = hb.x; ph.w = hb.y;
    pl.x = la.x; pl.y = la.y; pl.z = lb.x; pl.w = lb.y;
    Wh[i] = ph;
    Wl[i] = pl;
}

// i2h: [u][400][2048] f32 -> [u][416][2048] hi/lo; all divisors constant
#define I2H_OUT8 ((int)(24 * IVP * 2048 / 8))
__global__ void wsplit_i2h(const float* __restrict__ W, uint4* __restrict__ Wh,
                           uint4* __restrict__ Wl) {
    int i = blockIdx.x * blockDim.x + threadIdx.x;
    if (i >= I2H_OUT8) return;
    int u = i / (IVP * 2048 / 8);
    int r = i - u * (IVP * 2048 / 8);
    int k = r / (2048 / 8);
    int n8 = r - k * (2048 / 8);
    float4 a, b;
    if (k < IVv) {
        const float* src = W + ((size_t)u * IVv + k) * 2048 + n8 * 8;
        a = *(const float4*)src;
        b = *(const float4*)(src + 4);
    } else {
        a = make_float4(0.f, 0.f, 0.f, 0.f);
        b = a;
    }
    uint2 ha, la, hb, lb;
    split4(a, ha, la);
    split4(b, hb, lb);
    uint4 ph, pl;
    ph.x = ha.x; ph.y = ha.y; ph.z = hb.x; ph.w = hb.y;
    pl.x = la.x; pl.y = la.y; pl.z = lb.x; pl.w = lb.y;
    Wh[i] = ph;
    Wl[i] = pl;
}

// ===================== bf16-split tensor-core GEMM (mma.sync) =====================
// D[(b*U+u)*ldc + n] = sum_k A(b,u,k) * W[u][k][n], hi/lo split, fp32 acc.
// CTA tile 128x128, 8 warps (2 M x 4 N), warp tile 64x32, BK=32, cp.async 2-stage.
// B tiles loaded from NATIVE row-major [k][n]; fragments via ldmatrix.trans.
// mode 0: store C. mode 1: out = mask ? acc+ht : hs_in. mode 2: blockIdx.x picks
//         (Bh1,C) vs (Bh2,C2), n0=0, single pass.
#define BKc   32
#define BKp   40
#define BNp   136
#define AST   (128 * BKp * 2)     // 10240 B per A tile
#define BST   (BKc * BNp * 2)     // 8704 B per B tile
#define STAGE (2 * AST + 2 * BST) // 37888 B
#define SMEMT (2 * STAGE)         // 75776 B

extern __shared__ char gsm[];

struct GArgs {
    const bf16 *Auh, *Aul, *Buh, *Bul;  // B bases already offset by n0
    int K, ars, ldw;
};

__device__ __forceinline__ void issue_loads(const GArgs& ga, uint32_t sbuf,
                                            int k0, int tid) {
    #pragma unroll
    for (int h = 0; h < 2; h++) {
        int c = tid + h * 256;
        // A: 512 chunks/array: row = c>>2 (0..127), seg = c&3
        int arow = c >> 2, aseg = c & 3;
        uint32_t ad = sbuf + (uint32_t)(arow * (BKp * 2) + aseg * 16);
        const bf16* a_h = ga.Auh + (size_t)arow * ga.ars + k0 + aseg * 8;
        const bf16* a_l = ga.Aul + (size_t)arow * ga.ars + k0 + aseg * 8;
        cp16(ad,       a_h);
        cp16(ad + AST, a_l);
        // B: 512 chunks/array: row = c>>4 (0..31), nseg = c&15
        int brow = c >> 4, bseg = c & 15;
        uint32_t bd = sbuf + 2 * AST + (uint32_t)(brow * (BNp * 2) + bseg * 16);
        const bf16* b_h = ga.Buh + (size_t)(k0 + brow) * ga.ldw + bseg * 8;
        const bf16* b_l = ga.Bul + (size_t)(k0 + brow) * ga.ldw + bseg * 8;
        cp16(bd,       b_h);
        cp16(bd + BST, b_l);
    }
    cp_commit();
}

__global__ void __launch_bounds__(256) bgemm(
    const bf16* __restrict__ Ah1, const bf16* __restrict__ Al1, int a1_uoff, int a1_rs,
    const bf16* __restrict__ Bh1, const bf16* __restrict__ Bl1, int K1,
    const bf16* __restrict__ Ah2, const bf16* __restrict__ Al2, int a2_uoff, int a2_rs,
    const bf16* __restrict__ Bh2, const bf16* __restrict__ Bl2, int K2,
    int ldc, float* __restrict__ C, int mode, float* __restrict__ C2,
    const float* __restrict__ ht, const float* __restrict__ mk,
    const float* __restrict__ hs_in, float* __restrict__ outp)
{
    uint32_t sb = smem_u32(gsm);
    int tid  = threadIdx.x;
    int lane = tid & 31, wid = tid >> 5;
    int wm = wid & 1, wn = wid >> 1;
    int u = blockIdx.z, m0 = blockIdx.y * 128;
    int n0;
    const bf16 *Bh = Bh1, *Bl = Bl1;
    float* Csel = C;
    if (mode == 2) {
        n0 = 0;
        if (blockIdx.x) { Bh = Bh2; Bl = Bl2; Csel = C2; }
    } else {
        n0 = blockIdx.x * 128;
    }

    float acc[4][4][4];
    #pragma unroll
    for (int i = 0; i < 4; i++)
        #pragma unroll
        for (int j = 0; j < 4; j++)
            #pragma unroll
            for (int k = 0; k < 4; k++) acc[i][j][k] = 0.f;

    // lane-dependent ldmatrix offsets
    int a_ro = lane & 15, a_cg = lane >> 4;
    int b_kr = (lane & 7) + 8 * ((lane >> 3) & 1);  // k-row within 16-k step

    int npass = (mode != 2 && K2 > 0) ? 2 : 1;
    #pragma unroll 1
    for (int pass = 0; pass < npass; pass++) {
        GArgs ga;
        if (pass == 0) {
            ga.Auh = Ah1 + (size_t)u * a1_uoff + (size_t)m0 * a1_rs;
            ga.Aul = Al1 + (size_t)u * a1_uoff + (size_t)m0 * a1_rs;
            ga.Buh = Bh + (size_t)u * K1 * ldc + n0;
            ga.Bul = Bl + (size_t)u * K1 * ldc + n0;
            ga.K = K1; ga.ars = a1_rs; ga.ldw = ldc;
        } else {
            ga.Auh = Ah2 + (size_t)u * a2_uoff + (size_t)m0 * a2_rs;
            ga.Aul = Al2 + (size_t)u * a2_uoff + (size_t)m0 * a2_rs;
            ga.Buh = Bh2 + (size_t)u * K2 * ldc + n0;
            ga.Bul = Bl2 + (size_t)u * K2 * ldc + n0;
            ga.K = K2; ga.ars = a2_rs; ga.ldw = ldc;
        }
        int T = ga.K / BKc;

        issue_loads(ga, sb, 0, tid);

        #pragma unroll 1
        for (int t = 0; t < T; t++) {
            uint32_t scur = sb + (uint32_t)((t & 1) * STAGE);
            if (t + 1 < T) {
                issue_loads(ga, sb + (uint32_t)(((t + 1) & 1) * STAGE), (t + 1) * BKc, tid);
                cp_wait1();
            } else {
                cp_wait0();
            }
            __syncthreads();

            #pragma unroll
            for (int ks = 0; ks < 2; ks++) {
                int koff = ks * 16;
                uint32_t a_h[4][4], a_l[4][4], b_h[4][2], b_l[4][2];
                #pragma unroll
                for (int mt = 0; mt < 4; mt++) {
                    uint32_t ad = scur +
                        (uint32_t)(((wm * 64 + mt * 16 + a_ro) * BKp + koff + a_cg * 8) * 2);
                    ldsm_x4(a_h[mt], ad);
                    ldsm_x4(a_l[mt], ad + AST);
                }
                #pragma unroll
                for (int nt = 0; nt < 4; nt++) {
                    uint32_t bd = scur + 2 * AST +
                        (uint32_t)(((koff + b_kr) * BNp + wn * 32 + nt * 8) * 2);
                    ldsm_x2_trans(b_h[nt], bd);
                    ldsm_x2_trans(b_l[nt], bd + BST);
                }
                // split-major ordering: consecutive MMAs hit independent accumulators
                #pragma unroll
                for (int mt = 0; mt < 4; mt++)
                    #pragma unroll
                    for (int nt = 0; nt < 4; nt++)
                        mma_bf16(acc[mt][nt], a_h[mt], b_h[nt]);
                #pragma unroll
                for (int mt = 0; mt < 4; mt++)
                    #pragma unroll
                    for (int nt = 0; nt < 4; nt++)
                        mma_bf16(acc[mt][nt], a_h[mt], b_l[nt]);
                #pragma unroll
                for (int mt = 0; mt < 4; mt++)
                    #pragma unroll
                    for (int nt = 0; nt < 4; nt++)
                        mma_bf16(acc[mt][nt], a_l[mt], b_h[nt]);
            }
            __syncthreads();
        }
    }

    // epilogue: D fragment m16n8 -> rows lane>>2 (+8), cols (lane&3)*2
    #pragma unroll
    for (int mt = 0; mt < 4; mt++) {
        #pragma unroll
        for (int half = 0; half < 2; half++) {
            int row = m0 + wm * 64 + mt * 16 + (lane >> 2) + 8 * half;
            int bu = row * Uu + u;
            bool sel = (mode == 1) ? (mk[bu] != 0.f) : false;
            #pragma unroll
            for (int nt = 0; nt < 4; nt++) {
                int col = n0 + wn * 32 + nt * 8 + (lane & 3) * 2;
                size_t idx = (size_t)bu * ldc + col;
                float2 v;
                v.x = acc[mt][nt][2 * half + 0];
                v.y = acc[mt][nt][2 * half + 1];
                if (mode == 1) {
                    if (sel) {
                        float2 h = *(const float2*)&ht[idx];
                        v.x += h.x; v.y += h.y;
                    } else {
                        v = *(const float2*)&hs_in[idx];
                    }
                    *(float2*)&outp[idx] = v;
                } else {
                    *(float2*)&Csel[idx] = v;
                }
            }
        }
    }
}

// ---------------- LSTM gates + cs_new + ht (f32 + bf16 hi/lo) ----------------
__global__ void gates_kernel(const float* __restrict__ cs, float* __restrict__ out_cs) {
    int idx = blockIdx.x * blockDim.x + threadIdx.x;
    if (idx >= Bsz * Uu * Hh) return;
    int h  = idx % Hh;
    int bu = idx / Hh;
    size_t base = (size_t)bu * 4 * Hh;
    float pi = g_pre[base + h];
    float pf = g_pre[base + Hh + h];
    float po = g_pre[base + 2 * Hh + h];
    float pg = g_pre[base + 3 * Hh + h];
    float it = 1.f / (1.f + expf(-pi));
    float ft = 1.f / (1.f + expf(-pf));
    float ot = 1.f / (1.f + expf(-po));
    float gt = tanhf(pg);
    float c  = cs[idx] * ft + it * gt;
    float htv = ot * tanhf(c);
    g_ht[idx] = htv;
    bf16 hh = __float2bfloat16_rn(htv);
    g_hth[idx] = hh;
    g_htl[idx] = __float2bfloat16_rn(htv - __bfloat162float(hh));
    out_cs[idx] = (g_mask[bu] != 0.f) ? c : cs[idx];
}

// ---------------- communication attention: ctx (bf16 hi/lo out) --------------
__global__ void __launch_bounds__(256) attn_kernel() {
    int b = blockIdx.x >> 2;
    int head = blockIdx.x & 3;
    __shared__ float qcs[Uu][CKk + 1], kcs[Uu][CKk + 1], att[Uu][Uu];
    int tid = threadIdx.x;
    for (int i = tid; i < Uu * CKk; i += 256) {
        int uu = i / CKk, c = i % CKk;
        size_t base = (size_t)(b * Uu + uu) * (NCHh * CKk) + head * CKk + c;
        qcs[uu][c] = g_qc[base];
        kcs[uu][c] = g_kc[base];
    }
    __syncthreads();
    for (int i = tid; i < Uu * Uu; i += 256) {
        int uu = i / Uu, t = i % Uu;
        float s = 0.f;
        #pragma unroll
        for (int c = 0; c < CKk; c++) s += qcs[uu][c] * kcs[t][c];
        att[uu][t] = s * 0.17677669529663687f;
    }
    __syncthreads();
    if (tid < Uu) {
        float m = -1e30f;
        #pragma unroll
        for (int t = 0; t < Uu; t++) m = fmaxf(m, att[tid][t]);
        float sum = 0.f;
        #pragma unroll
        for (int t = 0; t < Uu; t++) {
            float e = expf(att[tid][t] - m);
            att[tid][t] = e;
            sum += e;
        }
        float inv = 1.f / sum;
        #pragma unroll
        for (int t = 0; t < Uu; t++) att[tid][t] *= inv;
    }
    __syncthreads();
    float accx[Uu], accy[Uu];
    #pragma unroll
    for (int uu = 0; uu < Uu; uu++) { accx[uu] = 0.f; accy[uu] = 0.f; }
    int v0 = tid * 2;
    #pragma unroll 4
    for (int t = 0; t < Uu; t++) {
        float2 vv = *(const float2*)&g_vc[(size_t)(b * Uu + t) * (NCHh * CVv) + head * CVv + v0];
        #pragma unroll
        for (int uu = 0; uu < Uu; uu++) {
            float a = att[uu][t];
            accx[uu] += a * vv.x;
            accy[uu] += a * vv.y;
        }
    }
    #pragma unroll
    for (int uu = 0; uu < Uu; uu++) {
        size_t o = (size_t)(b * Uu + uu) * (NCHh * CVv) + head * CVv + v0;
        bf16 hx = __float2bfloat16_rn(accx[uu]);
        bf16 hy = __float2bfloat16_rn(accy[uu]);
        g_ctx_h[o]     = hx;
        g_ctx_h[o + 1] = hy;
        g_ctx_l[o]     = __float2bfloat16_rn(accx[uu] - __bfloat162float(hx));
        g_ctx_l[o + 1] = __float2bfloat16_rn(accy[uu] - __bfloat162float(hy));
    }
}

// ---------------- launch ----------------
extern "C" void kernel_launch(void* const* d_in, const int* in_sizes, int n_in,
                              void* d_out, int out_size) {
    const float* x       = (const float*)d_in[0];
    const float* hs      = (const float*)d_in[1];
    const float* cs      = (const float*)d_in[2];
    const float* key_w   = (const float*)d_in[3];
    const float* key_b   = (const float*)d_in[4];
    const float* value_w = (const float*)d_in[5];
    const float* value_b = (const float*)d_in[6];
    const float* query_w = (const float*)d_in[7];
    const float* i2h_w   = (const float*)d_in[8];
    const float* h2h_w   = (const float*)d_in[9];
    const float* qc_w    = (const float*)d_in[10];
    const float* kc_w    = (const float*)d_in[11];
    const float* vc_w    = (const float*)d_in[12];
    const float* co_w    = (const float*)d_in[13];
    float* out    = (float*)d_out;
    float* out_hs = out;
    float* out_cs = out + (size_t)Bsz * Uu * Hh;

    cudaFuncSetAttribute(bgemm, cudaFuncAttributeMaxDynamicSharedMemorySize, SMEMT);

    float *p_pre, *p_ht, *p_qc, *p_kc, *p_vc, *p_mask;
    cudaGetSymbolAddress((void**)&p_pre,  g_pre);
    cudaGetSymbolAddress((void**)&p_ht,   g_ht);
    cudaGetSymbolAddress((void**)&p_qc,   g_qc);
    cudaGetSymbolAddress((void**)&p_kc,   g_kc);
    cudaGetSymbolAddress((void**)&p_vc,   g_vc);
    cudaGetSymbolAddress((void**)&p_mask, g_mask);
    bf16 *p_inp_h, *p_inp_l, *p_hs_h, *p_hs_l, *p_hth, *p_htl, *p_ctx_h, *p_ctx_l;
    cudaGetSymbolAddress((void**)&p_inp_h, g_inp_h);
    cudaGetSymbolAddress((void**)&p_inp_l, g_inp_l);
    cudaGetSymbolAddress((void**)&p_hs_h,  g_hs_h);
    cudaGetSymbolAddress((void**)&p_hs_l,  g_hs_l);
    cudaGetSymbolAddress((void**)&p_hth,   g_hth);
    cudaGetSymbolAddress((void**)&p_htl,   g_htl);
    cudaGetSymbolAddress((void**)&p_ctx_h, g_ctx_h);
    cudaGetSymbolAddress((void**)&p_ctx_l, g_ctx_l);
    bf16 *w_i2h_h, *w_i2h_l, *w_h2h_h, *w_h2h_l, *w_qc_h, *w_qc_l,
         *w_kc_h, *w_kc_l, *w_vc_h, *w_vc_l, *w_co_h, *w_co_l;
    cudaGetSymbolAddress((void**)&w_i2h_h, g_i2h_h);
    cudaGetSymbolAddress((void**)&w_i2h_l, g_i2h_l);
    cudaGetSymbolAddress((void**)&w_h2h_h, g_h2h_h);
    cudaGetSymbolAddress((void**)&w_h2h_l, g_h2h_l);
    cudaGetSymbolAddress((void**)&w_qc_h,  g_qcw_h);
    cudaGetSymbolAddress((void**)&w_qc_l,  g_qcw_l);
    cudaGetSymbolAddress((void**)&w_kc_h,  g_kcw_h);
    cudaGetSymbolAddress((void**)&w_kc_l,  g_kcw_l);
    cudaGetSymbolAddress((void**)&w_vc_h,  g_vcw_h);
    cudaGetSymbolAddress((void**)&w_vc_l,  g_vcw_l);
    cudaGetSymbolAddress((void**)&w_co_h,  g_cow_h);
    cudaGetSymbolAddress((void**)&w_co_l,  g_cow_l);

    // --- fast streaming weight split ---
    {
        int n8;
        n8 = (int)(H2H_SZ / 8);
        wsplit_stream<<<(n8 + 255) / 256, 256>>>((const float4*)h2h_w, (uint4*)w_h2h_h, (uint4*)w_h2h_l, n8);
        n8 = (int)(QCW_SZ / 8);
        wsplit_stream<<<(n8 + 255) / 256, 256>>>((const float4*)qc_w, (uint4*)w_qc_h, (uint4*)w_qc_l, n8);
        wsplit_stream<<<(n8 + 255) / 256, 256>>>((const float4*)kc_w, (uint4*)w_kc_h, (uint4*)w_kc_l, n8);
        n8 = (int)(VCW_SZ / 8);
        wsplit_stream<<<(n8 + 255) / 256, 256>>>((const float4*)vc_w, (uint4*)w_vc_h, (uint4*)w_vc_l, n8);
        n8 = (int)(COW_SZ / 8);
        wsplit_stream<<<(n8 + 255) / 256, 256>>>((const float4*)co_w, (uint4*)w_co_h, (uint4*)w_co_l, n8);
        wsplit_i2h<<<(I2H_OUT8 + 255) / 256, 256>>>(i2h_w, (uint4*)w_i2h_h, (uint4*)w_i2h_l);
    }

    // --- stage A ---
    kv_kernel<<<Bsz, 512>>>(x, key_w, key_b, value_w, value_b);
    qscore_kernel<<<Bsz * Uu, 64>>>(hs, query_w, key_b);
    topk_kernel<<<1, Bsz>>>();
    inp_kernel<<<(Bsz * Uu * IVP + 255) / 256, 256>>>(value_b);
    hsconv_kernel<<<(Bsz * Uu * Hh + 255) / 256, 256>>>(hs);

    // --- preact = inp@i2h + hs@h2h (dual pass, K=416+512) ---
    bgemm<<<dim3(2048 / 128, Bsz / 128, Uu), 256, SMEMT>>>(
        p_inp_h, p_inp_l, IVP, Uu * IVP, w_i2h_h, w_i2h_l, IVP,
        p_hs_h,  p_hs_l,  Hh,  Uu * Hh,  w_h2h_h, w_h2h_l, Hh,
        2048, p_pre, 0, nullptr, nullptr, nullptr, nullptr, nullptr);

    gates_kernel<<<(Bsz * Uu * Hh + 255) / 256, 256>>>(cs, out_cs);

    // --- qc & kc merged (N=128 each, mode 2) ---
    bgemm<<<dim3(2, Bsz / 128, Uu), 256, SMEMT>>>(
        p_hth, p_htl, Hh, Uu * Hh, w_qc_h, w_qc_l, Hh,
        nullptr, nullptr, 0, 0, w_kc_h, w_kc_l, 0,
        128, p_qc, 2, p_kc, nullptr, nullptr, nullptr, nullptr);

    // --- vc (N=2048) ---
    bgemm<<<dim3(2048 / 128, Bsz / 128, Uu), 256, SMEMT>>>(
        p_hth, p_htl, Hh, Uu * Hh, w_vc_h, w_vc_l, Hh,
        nullptr, nullptr, 0, 0, nullptr, nullptr, 0,
        2048, p_vc, 0, nullptr, nullptr, nullptr, nullptr, nullptr);

    attn_kernel<<<Bsz * NCHh, 256>>>();

    // --- co GEMM with fused hs_new epilogue ---
    bgemm<<<dim3(512 / 128, Bsz / 128, Uu), 256, SMEMT>>>(
        p_ctx_h, p_ctx_l, NCHh * CVv, Uu * NCHh * CVv, w_co_h, w_co_l, NCHh * CVv,
        nullptr, nullptr, 0, 0, nullptr, nullptr, 0,
        512, nullptr, 1, nullptr, p_ht, p_mask, hs, out_hs);
}

// round 16
// speedup vs baseline: 1.1336x; 1.0381x over previous
#include <cuda_runtime.h>
#include <cuda_bf16.h>
#include <math.h>
#include <stddef.h>
#include <stdint.h>

#define Bsz 256
#define Dd  512
#define Hh  512
#define Uu  24
#define Kk  8
#define IKk 64
#define IVv 400
#define IVP 416        // IVv padded to multiple of 32
#define CKk 32
#define NCHh 4
#define CVv 512

typedef __nv_bfloat16 bf16;

// ---------------- fp32 scratch ----------------
__device__ float g_k0[Bsz * IKk];
__device__ float g_v0[Bsz * IVv];
__device__ float g_s0[Bsz * Uu];
__device__ float g_p0[Bsz * Uu];
__device__ float g_mask[Bsz * Uu];
__device__ float g_pre[(size_t)Bsz * Uu * 4 * Hh];   // 50 MB
__device__ float g_ht[Bsz * Uu * Hh];
__device__ float g_qc[Bsz * Uu * NCHh * CKk];
__device__ float g_kc[Bsz * Uu * NCHh * CKk];
__device__ float g_vc[(size_t)Bsz * Uu * NCHh * CVv];  // 50 MB

// ---------------- bf16 hi/lo activations (A operands) -------------
__device__ __align__(16) bf16 g_inp_h[Bsz * Uu * IVP];
__device__ __align__(16) bf16 g_inp_l[Bsz * Uu * IVP];
__device__ __align__(16) bf16 g_hs_h[Bsz * Uu * Hh];
__device__ __align__(16) bf16 g_hs_l[Bsz * Uu * Hh];
__device__ __align__(16) bf16 g_hth[Bsz * Uu * Hh];
__device__ __align__(16) bf16 g_htl[Bsz * Uu * Hh];
__device__ __align__(16) bf16 g_ctx_h[(size_t)Bsz * Uu * NCHh * CVv];
__device__ __align__(16) bf16 g_ctx_l[(size_t)Bsz * Uu * NCHh * CVv];

// ---------------- bf16 hi/lo weights, NATIVE [u][Kp][N] layout ---------
#define I2H_SZ ((size_t)24 * IVP * 2048)
#define H2H_SZ ((size_t)24 * 512 * 2048)
#define QCW_SZ ((size_t)24 * 512 * 128)
#define VCW_SZ ((size_t)24 * 512 * 2048)
#define COW_SZ ((size_t)24 * 2048 * 512)
__device__ __align__(16) bf16 g_i2h_h[I2H_SZ]; __device__ __align__(16) bf16 g_i2h_l[I2H_SZ];
__device__ __align__(16) bf16 g_h2h_h[H2H_SZ]; __device__ __align__(16) bf16 g_h2h_l[H2H_SZ];
__device__ __align__(16) bf16 g_qcw_h[QCW_SZ]; __device__ __align__(16) bf16 g_qcw_l[QCW_SZ];
__device__ __align__(16) bf16 g_kcw_h[QCW_SZ]; __device__ __align__(16) bf16 g_kcw_l[QCW_SZ];
__device__ __align__(16) bf16 g_vcw_h[VCW_SZ]; __device__ __align__(16) bf16 g_vcw_l[VCW_SZ];
__device__ __align__(16) bf16 g_cow_h[COW_SZ]; __device__ __align__(16) bf16 g_cow_l[COW_SZ];

// ===================== PTX helpers (baseline sm_80+ only) =====================
__device__ __forceinline__ uint32_t smem_u32(const void* p) {
    uint32_t a;
    asm("{ .reg .u64 t; cvta.to.shared.u64 t, %1; cvt.u32.u64 %0, t; }" : "=r"(a) : "l"(p));
    return a;
}
__device__ __forceinline__ void cp16(uint32_t dst, const void* src) {
    asm volatile("cp.async.cg.shared.global [%0], [%1], 16;"
                 :: "r"(dst), "l"(__cvta_generic_to_global(src)) : "memory");
}
__device__ __forceinline__ void cp_commit() {
    asm volatile("cp.async.commit_group;" ::: "memory");
}
__device__ __forceinline__ void cp_wait0() {
    asm volatile("cp.async.wait_group 0;" ::: "memory");
}
__device__ __forceinline__ void cp_wait1() {
    asm volatile("cp.async.wait_group 1;" ::: "memory");
}
__device__ __forceinline__ void cp_wait2() {
    asm volatile("cp.async.wait_group 2;" ::: "memory");
}
__device__ __forceinline__ void ldsm_x4(uint32_t* r, uint32_t addr) {
    asm volatile("ldmatrix.sync.aligned.m8n8.x4.shared.b16 {%0,%1,%2,%3}, [%4];"
                 : "=r"(r[0]), "=r"(r[1]), "=r"(r[2]), "=r"(r[3]) : "r"(addr));
}
__device__ __forceinline__ void ldsm_x2_trans(uint32_t* r, uint32_t addr) {
    asm volatile("ldmatrix.sync.aligned.m8n8.x2.trans.shared.b16 {%0,%1}, [%2];"
                 : "=r"(r[0]), "=r"(r[1]) : "r"(addr));
}
__device__ __forceinline__ void mma_bf16(float* d, const uint32_t* a, const uint32_t* b) {
    asm volatile(
        "mma.sync.aligned.m16n8k16.row.col.f32.bf16.bf16.f32 "
        "{%0,%1,%2,%3}, {%4,%5,%6,%7}, {%8,%9}, {%0,%1,%2,%3};"
        : "+f"(d[0]), "+f"(d[1]), "+f"(d[2]), "+f"(d[3])
        : "r"(a[0]), "r"(a[1]), "r"(a[2]), "r"(a[3]), "r"(b[0]), "r"(b[1]));
}

// ---------------- stage A: k0 = x@key_w+key_b, v0 = x@value_w+value_b ------
__global__ void kv_kernel(const float* __restrict__ x,
                          const float* __restrict__ key_w, const float* __restrict__ key_b,
                          const float* __restrict__ value_w, const float* __restrict__ value_b) {
    int b = blockIdx.x;
    __shared__ float xs[Dd];
    int tid = threadIdx.x; // 512
    xs[tid] = x[(size_t)b * Dd + tid];
    __syncthreads();
    if (tid < IVv) {
        float acc = value_b[tid];
        #pragma unroll 8
        for (int d = 0; d < Dd; d++) acc += xs[d] * value_w[(size_t)d * IVv + tid];
        g_v0[b * IVv + tid] = acc;
    } else if (tid < IVv + IKk) {
        int ik = tid - IVv;
        float acc = key_b[ik];
        #pragma unroll 8
        for (int d = 0; d < Dd; d++) acc += xs[d] * key_w[(size_t)d * IKk + ik];
        g_k0[b * IKk + ik] = acc;
    }
}

// ---------------- stage A: q, scores, probs ----------------
__global__ void qscore_kernel(const float* __restrict__ hs,
                              const float* __restrict__ query_w,
                              const float* __restrict__ key_b) {
    int bu = blockIdx.x;
    int b = bu / Uu, u = bu % Uu;
    int ik = threadIdx.x; // 64
    __shared__ float hss[Hh];
    for (int i = ik; i < Hh; i += 64) hss[i] = hs[(size_t)bu * Hh + i];
    __syncthreads();
    const float* qw = query_w + (size_t)u * Hh * IKk;
    float q = 0.f;
    #pragma unroll 8
    for (int d = 0; d < Hh; d++) q += hss[d] * qw[(size_t)d * IKk + ik];
    float p0 = q * g_k0[b * IKk + ik];
    float p1 = q * key_b[ik];
    #pragma unroll
    for (int off = 16; off > 0; off >>= 1) {
        p0 += __shfl_down_sync(0xffffffffu, p0, off);
        p1 += __shfl_down_sync(0xffffffffu, p1, off);
    }
    __shared__ float r0[2], r1[2];
    if ((ik & 31) == 0) { r0[ik >> 5] = p0; r1[ik >> 5] = p1; }
    __syncthreads();
    if (ik == 0) {
        float s0 = (r0[0] + r0[1]) * 0.125f;
        float s1 = (r1[0] + r1[1]) * 0.125f;
        g_s0[bu] = s0;
        float m = fmaxf(s0, s1);
        float e0 = expf(s0 - m), e1 = expf(s1 - m);
        g_p0[bu] = e0 / (e0 + e1);
    }
}

// ---------------- top-k mask ----------------
__global__ void topk_kernel() {
    int b = threadIdx.x;
    float s[Uu];
    #pragma unroll
    for (int u = 0; u < Uu; u++) s[u] = g_s0[b * Uu + u];
    #pragma unroll
    for (int u = 0; u < Uu; u++) {
        int cnt = 0;
        #pragma unroll
        for (int t = 0; t < Uu; t++)
            if (s[t] > s[u] || (s[t] == s[u] && t < u)) cnt++;
        g_mask[b * Uu + u] = (cnt < Kk) ? 1.f : 0.f;
    }
}

// ---------------- merged inp + hs conversion ----------------
#define INP_N (Bsz * Uu * IVP)
#define HS_N  (Bsz * Uu * Hh)
__global__ void inphs_kernel(const float* __restrict__ value_b,
                             const float* __restrict__ hs) {
    int idx = blockIdx.x * blockDim.x + threadIdx.x;
    if (idx < INP_N) {
        int iv = idx % IVP;
        int bu = idx / IVP;
        int b = bu / Uu;
        float v = 0.f;
        if (iv < IVv) {
            float p0 = g_p0[bu];
            v = p0 * g_v0[b * IVv + iv] + (1.f - p0) * value_b[iv];
            v *= g_mask[bu];
        }
        bf16 h = __float2bfloat16_rn(v);
        g_inp_h[idx] = h;
        g_inp_l[idx] = __float2bfloat16_rn(v - __bfloat162float(h));
    } else if (idx < INP_N + HS_N) {
        int j = idx - INP_N;
        float v = hs[j];
        bf16 h = __float2bfloat16_rn(v);
        g_hs_h[j] = h;
        g_hs_l[j] = __float2bfloat16_rn(v - __bfloat162float(h));
    }
}

// ---------------- single-launch streaming weight split ----------------
__device__ __forceinline__ void split4(float4 v, uint2& ph, uint2& pl) {
    bf16 h0 = __float2bfloat16_rn(v.x), h1 = __float2bfloat16_rn(v.y);
    bf16 h2 = __float2bfloat16_rn(v.z), h3 = __float2bfloat16_rn(v.w);
    bf16 l0 = __float2bfloat16_rn(v.x - __bfloat162float(h0));
    bf16 l1 = __float2bfloat16_rn(v.y - __bfloat162float(h1));
    bf16 l2 = __float2bfloat16_rn(v.z - __bfloat162float(h2));
    bf16 l3 = __float2bfloat16_rn(v.w - __bfloat162float(h3));
    ph.x = (uint32_t)__bfloat16_as_ushort(h0) | ((uint32_t)__bfloat16_as_ushort(h1) << 16);
    ph.y = (uint32_t)__bfloat16_as_ushort(h2) | ((uint32_t)__bfloat16_as_ushort(h3) << 16);
    pl.x = (uint32_t)__bfloat16_as_ushort(l0) | ((uint32_t)__bfloat16_as_ushort(l1) << 16);
    pl.y = (uint32_t)__bfloat16_as_ushort(l2) | ((uint32_t)__bfloat16_as_ushort(l3) << 16);
}
__device__ __forceinline__ void split8(const float4* src, uint4* dh, uint4* dl, int j) {
    float4 a = src[2 * j], b = src[2 * j + 1];
    uint2 ha, la, hb, lb;
    split4(a, ha, la);
    split4(b, hb, lb);
    uint4 ph, pl;
    ph.x = ha.x; ph.y = ha.y; ph.z = hb.x; ph.w = hb.y;
    pl.x = la.x; pl.y = la.y; pl.z = lb.x; pl.w = lb.y;
    dh[j] = ph;
    dl[j] = pl;
}

#define C_H2H ((int)(H2H_SZ / 8))
#define C_QC  ((int)(QCW_SZ / 8))
#define C_VC  ((int)(VCW_SZ / 8))
#define C_CO  ((int)(COW_SZ / 8))
#define C_I2H ((int)(24 * IVP * 2048 / 8))
#define B1 C_H2H
#define B2 (B1 + C_QC)
#define B3 (B2 + C_QC)
#define B4 (B3 + C_VC)
#define B5 (B4 + C_CO)
#define B6 (B5 + C_I2H)

__global__ void wsplit_all(const float* __restrict__ h2h, const float* __restrict__ qc,
                           const float* __restrict__ kc, const float* __restrict__ vc,
                           const float* __restrict__ co, const float* __restrict__ i2h) {
    int i = blockIdx.x * blockDim.x + threadIdx.x;
    if (i < B1) {
        split8((const float4*)h2h, (uint4*)g_h2h_h, (uint4*)g_h2h_l, i);
    } else if (i < B2) {
        split8((const float4*)qc, (uint4*)g_qcw_h, (uint4*)g_qcw_l, i - B1);
    } else if (i < B3) {
        split8((const float4*)kc, (uint4*)g_kcw_h, (uint4*)g_kcw_l, i - B2);
    } else if (i < B4) {
        split8((const float4*)vc, (uint4*)g_vcw_h, (uint4*)g_vcw_l, i - B3);
    } else if (i < B5) {
        split8((const float4*)co, (uint4*)g_cow_h, (uint4*)g_cow_l, i - B4);
    } else if (i < B6) {
        int j = i - B5;
        int u = j / (IVP * 2048 / 8);
        int r = j - u * (IVP * 2048 / 8);
        int k = r / (2048 / 8);
        int n8 = r - k * (2048 / 8);
        float4 a, b;
        if (k < IVv) {
            const float* src = i2h + ((size_t)u * IVv + k) * 2048 + n8 * 8;
            a = *(const float4*)src;
            b = *(const float4*)(src + 4);
        } else {
            a = make_float4(0.f, 0.f, 0.f, 0.f);
            b = a;
        }
        uint2 ha, la, hb, lb;
        split4(a, ha, la);
        split4(b, hb, lb);
        uint4 ph, pl;
        ph.x = ha.x; ph.y = ha.y; ph.z = hb.x; ph.w = hb.y;
        pl.x = la.x; pl.y = la.y; pl.z = lb.x; pl.w = lb.y;
        ((uint4*)g_i2h_h)[j] = ph;
        ((uint4*)g_i2h_l)[j] = pl;
    }
}

// ===================== bf16-split tensor-core GEMM (mma.sync) =====================
// D[(b*U+u)*ldo + n] = sum_k A(b,u,k) * W[u][k][n], hi/lo split, fp32 acc.
// CTA tile 128x128, 8 warps (2Mx4N), BK=32, 3-stage cp.async, ldmatrix.trans B.
// mode 0: store C (dual A/B pass if K2>0).
// mode 1: out = mask ? acc+ht : hs_in.
// mode 3: qkv dispatch: x==0 -> (Bh1,C,ld 128); x==1 -> (Bh2,C2,ld 128);
//         x>=2 -> (Bh3,C3,ld 2048, n0=(x-2)*128). Single pass, K=K1.
#define BKc   32
#define BKp   40
#define BNp   136
#define AST   (128 * BKp * 2)     // 10240 B per A tile
#define BST   (BKc * BNp * 2)     // 8704 B per B tile
#define STAGE (2 * AST + 2 * BST) // 37888 B
#define SMEMT (3 * STAGE)         // 113664 B

extern __shared__ char gsm[];

struct GArgs {
    const bf16 *Auh, *Aul, *Buh, *Bul;
    int K, ars, ldw;
};

__device__ __forceinline__ void issue_loads(const GArgs& ga, uint32_t sbuf,
                                            int k0, int tid) {
    #pragma unroll
    for (int h = 0; h < 2; h++) {
        int c = tid + h * 256;
        int arow = c >> 2, aseg = c & 3;
        uint32_t ad = sbuf + (uint32_t)(arow * (BKp * 2) + aseg * 16);
        cp16(ad,       ga.Auh + (size_t)arow * ga.ars + k0 + aseg * 8);
        cp16(ad + AST, ga.Aul + (size_t)arow * ga.ars + k0 + aseg * 8);
        int brow = c >> 4, bseg = c & 15;
        uint32_t bd = sbuf + 2 * AST + (uint32_t)(brow * (BNp * 2) + bseg * 16);
        cp16(bd,       ga.Buh + (size_t)(k0 + brow) * ga.ldw + bseg * 8);
        cp16(bd + BST, ga.Bul + (size_t)(k0 + brow) * ga.ldw + bseg * 8);
    }
    cp_commit();
}

__global__ void __launch_bounds__(256) bgemm(
    const bf16* __restrict__ Ah1, const bf16* __restrict__ Al1, int a1_uoff, int a1_rs,
    const bf16* __restrict__ Bh1, const bf16* __restrict__ Bl1, int K1,
    const bf16* __restrict__ Ah2, const bf16* __restrict__ Al2, int a2_uoff, int a2_rs,
    const bf16* __restrict__ Bh2, const bf16* __restrict__ Bl2, int K2,
    const bf16* __restrict__ Bh3, const bf16* __restrict__ Bl3,
    int ldc, float* __restrict__ C, int mode,
    float* __restrict__ C2, float* __restrict__ C3,
    const float* __restrict__ ht, const float* __restrict__ mk,
    const float* __restrict__ hs_in, float* __restrict__ outp)
{
    uint32_t sb = smem_u32(gsm);
    int tid  = threadIdx.x;
    int lane = tid & 31, wid = tid >> 5;
    int wm = wid & 1, wn = wid >> 1;
    int u = blockIdx.z, m0 = blockIdx.y * 128;
    int bx = blockIdx.x;

    const bf16 *Bh, *Bl;
    float* Cs;
    int ldo, n0;
    if (mode == 3) {
        if (bx == 0)      { Bh = Bh1; Bl = Bl1; Cs = C;  ldo = 128;  n0 = 0; }
        else if (bx == 1) { Bh = Bh2; Bl = Bl2; Cs = C2; ldo = 128;  n0 = 0; }
        else              { Bh = Bh3; Bl = Bl3; Cs = C3; ldo = 2048; n0 = (bx - 2) * 128; }
    } else {
        Bh = Bh1; Bl = Bl1; Cs = C; ldo = ldc; n0 = bx * 128;
    }

    float acc[4][4][4];
    #pragma unroll
    for (int i = 0; i < 4; i++)
        #pragma unroll
        for (int j = 0; j < 4; j++)
            #pragma unroll
            for (int k = 0; k < 4; k++) acc[i][j][k] = 0.f;

    int a_ro = lane & 15, a_cg = lane >> 4;
    int b_kr = (lane & 7) + 8 * ((lane >> 3) & 1);

    int npass = (mode == 0 && K2 > 0) ? 2 : 1;
    #pragma unroll 1
    for (int pass = 0; pass < npass; pass++) {
        GArgs ga;
        if (pass == 0) {
            ga.Auh = Ah1 + (size_t)u * a1_uoff + (size_t)m0 * a1_rs;
            ga.Aul = Al1 + (size_t)u * a1_uoff + (size_t)m0 * a1_rs;
            ga.Buh = Bh + (size_t)u * K1 * ldo + n0;
            ga.Bul = Bl + (size_t)u * K1 * ldo + n0;
            ga.K = K1; ga.ars = a1_rs; ga.ldw = ldo;
        } else {
            ga.Auh = Ah2 + (size_t)u * a2_uoff + (size_t)m0 * a2_rs;
            ga.Aul = Al2 + (size_t)u * a2_uoff + (size_t)m0 * a2_rs;
            ga.Buh = Bh2 + (size_t)u * K2 * ldo + n0;
            ga.Bul = Bl2 + (size_t)u * K2 * ldo + n0;
            ga.K = K2; ga.ars = a2_rs; ga.ldw = ldo;
        }
        int T = ga.K / BKc;

        issue_loads(ga, sb, 0, tid);
        if (T > 1) issue_loads(ga, sb + STAGE, BKc, tid);

        #pragma unroll 1
        for (int t = 0; t < T; t++) {
            uint32_t scur = sb + (uint32_t)((t % 3) * STAGE);
            if (t + 2 < T) {
                issue_loads(ga, sb + (uint32_t)(((t + 2) % 3) * STAGE), (t + 2) * BKc, tid);
                cp_wait2();
            } else if (t + 1 < T) {
                cp_wait1();
            } else {
                cp_wait0();
            }
            __syncthreads();

            #pragma unroll
            for (int ks = 0; ks < 2; ks++) {
                int koff = ks * 16;
                uint32_t a_h[4][4], a_l[4][4], b_h[4][2], b_l[4][2];
                #pragma unroll
                for (int mt = 0; mt < 4; mt++) {
                    uint32_t ad = scur +
                        (uint32_t)(((wm * 64 + mt * 16 + a_ro) * BKp + koff + a_cg * 8) * 2);
                    ldsm_x4(a_h[mt], ad);
                    ldsm_x4(a_l[mt], ad + AST);
                }
                #pragma unroll
                for (int nt = 0; nt < 4; nt++) {
                    uint32_t bd = scur + 2 * AST +
                        (uint32_t)(((koff + b_kr) * BNp + wn * 32 + nt * 8) * 2);
                    ldsm_x2_trans(b_h[nt], bd);
                    ldsm_x2_trans(b_l[nt], bd + BST);
                }
                #pragma unroll
                for (int mt = 0; mt < 4; mt++)
                    #pragma unroll
                    for (int nt = 0; nt < 4; nt++)
                        mma_bf16(acc[mt][nt], a_h[mt], b_h[nt]);
                #pragma unroll
                for (int mt = 0; mt < 4; mt++)
                    #pragma unroll
                    for (int nt = 0; nt < 4; nt++)
                        mma_bf16(acc[mt][nt], a_h[mt], b_l[nt]);
                #pragma unroll
                for (int mt = 0; mt < 4; mt++)
                    #pragma unroll
                    for (int nt = 0; nt < 4; nt++)
                        mma_bf16(acc[mt][nt], a_l[mt], b_h[nt]);
            }
            __syncthreads();
        }
    }

    // epilogue: D fragment m16n8 -> rows lane>>2 (+8), cols (lane&3)*2
    #pragma unroll
    for (int mt = 0; mt < 4; mt++) {
        #pragma unroll
        for (int half = 0; half < 2; half++) {
            int row = m0 + wm * 64 + mt * 16 + (lane >> 2) + 8 * half;
            int bu = row * Uu + u;
            bool sel = (mode == 1) ? (mk[bu] != 0.f) : false;
            #pragma unroll
            for (int nt = 0; nt < 4; nt++) {
                int col = n0 + wn * 32 + nt * 8 + (lane & 3) * 2;
                size_t idx = (size_t)bu * ldo + col;
                float2 v;
                v.x = acc[mt][nt][2 * half + 0];
                v.y = acc[mt][nt][2 * half + 1];
                if (mode == 1) {
                    if (sel) {
                        float2 h = *(const float2*)&ht[idx];
                        v.x += h.x; v.y += h.y;
                    } else {
                        v = *(const float2*)&hs_in[idx];
                    }
                    *(float2*)&outp[idx] = v;
                } else {
                    *(float2*)&Cs[idx] = v;
                }
            }
        }
    }
}

// ---------------- LSTM gates + cs_new + ht (f32 + bf16 hi/lo) ----------------
__global__ void gates_kernel(const float* __restrict__ cs, float* __restrict__ out_cs) {
    int idx = blockIdx.x * blockDim.x + threadIdx.x;
    if (idx >= Bsz * Uu * Hh) return;
    int h  = idx % Hh;
    int bu = idx / Hh;
    size_t base = (size_t)bu * 4 * Hh;
    float pi = g_pre[base + h];
    float pf = g_pre[base + Hh + h];
    float po = g_pre[base + 2 * Hh + h];
    float pg = g_pre[base + 3 * Hh + h];
    float it = 1.f / (1.f + expf(-pi));
    float ft = 1.f / (1.f + expf(-pf));
    float ot = 1.f / (1.f + expf(-po));
    float gt = tanhf(pg);
    float c  = cs[idx] * ft + it * gt;
    float htv = ot * tanhf(c);
    g_ht[idx] = htv;
    bf16 hh = __float2bfloat16_rn(htv);
    g_hth[idx] = hh;
    g_htl[idx] = __float2bfloat16_rn(htv - __bfloat162float(hh));
    out_cs[idx] = (g_mask[bu] != 0.f) ? c : cs[idx];
}

// ---------------- communication attention: ctx (bf16 hi/lo out) --------------
__global__ void __launch_bounds__(256) attn_kernel() {
    int b = blockIdx.x >> 2;
    int head = blockIdx.x & 3;
    __shared__ float qcs[Uu][CKk + 1], kcs[Uu][CKk + 1], att[Uu][Uu];
    int tid = threadIdx.x;
    for (int i = tid; i < Uu * CKk; i += 256) {
        int uu = i / CKk, c = i % CKk;
        size_t base = (size_t)(b * Uu + uu) * (NCHh * CKk) + head * CKk + c;
        qcs[uu][c] = g_qc[base];
        kcs[uu][c] = g_kc[base];
    }
    __syncthreads();
    for (int i = tid; i < Uu * Uu; i += 256) {
        int uu = i / Uu, t = i % Uu;
        float s = 0.f;
        #pragma unroll
        for (int c = 0; c < CKk; c++) s += qcs[uu][c] * kcs[t][c];
        att[uu][t] = s * 0.17677669529663687f;
    }
    __syncthreads();
    if (tid < Uu) {
        float m = -1e30f;
        #pragma unroll
        for (int t = 0; t < Uu; t++) m = fmaxf(m, att[tid][t]);
        float sum = 0.f;
        #pragma unroll
        for (int t = 0; t < Uu; t++) {
            float e = expf(att[tid][t] - m);
            att[tid][t] = e;
            sum += e;
        }
        float inv = 1.f / sum;
        #pragma unroll
        for (int t = 0; t < Uu; t++) att[tid][t] *= inv;
    }
    __syncthreads();
    float accx[Uu], accy[Uu];
    #pragma unroll
    for (int uu = 0; uu < Uu; uu++) { accx[uu] = 0.f; accy[uu] = 0.f; }
    int v0 = tid * 2;
    #pragma unroll 4
    for (int t = 0; t < Uu; t++) {
        float2 vv = *(const float2*)&g_vc[(size_t)(b * Uu + t) * (NCHh * CVv) + head * CVv + v0];
        #pragma unroll
        for (int uu = 0; uu < Uu; uu++) {
            float a = att[uu][t];
            accx[uu] += a * vv.x;
            accy[uu] += a * vv.y;
        }
    }
    #pragma unroll
    for (int uu = 0; uu < Uu; uu++) {
        size_t o = (size_t)(b * Uu + uu) * (NCHh * CVv) + head * CVv + v0;
        bf16 hx = __float2bfloat16_rn(accx[uu]);
        bf16 hy = __float2bfloat16_rn(accy[uu]);
        g_ctx_h[o]     = hx;
        g_ctx_h[o + 1] = hy;
        g_ctx_l[o]     = __float2bfloat16_rn(accx[uu] - __bfloat162float(hx));
        g_ctx_l[o + 1] = __float2bfloat16_rn(accy[uu] - __bfloat162float(hy));
    }
}

// ---------------- launch ----------------
extern "C" void kernel_launch(void* const* d_in, const int* in_sizes, int n_in,
                              void* d_out, int out_size) {
    const float* x       = (const float*)d_in[0];
    const float* hs      = (const float*)d_in[1];
    const float* cs      = (const float*)d_in[2];
    const float* key_w   = (const float*)d_in[3];
    const float* key_b   = (const float*)d_in[4];
    const float* value_w = (const float*)d_in[5];
    const float* value_b = (const float*)d_in[6];
    const float* query_w = (const float*)d_in[7];
    const float* i2h_w   = (const float*)d_in[8];
    const float* h2h_w   = (const float*)d_in[9];
    const float* qc_w    = (const float*)d_in[10];
    const float* kc_w    = (const float*)d_in[11];
    const float* vc_w    = (const float*)d_in[12];
    const float* co_w    = (const float*)d_in[13];
    float* out    = (float*)d_out;
    float* out_hs = out;
    float* out_cs = out + (size_t)Bsz * Uu * Hh;

    cudaFuncSetAttribute(bgemm, cudaFuncAttributeMaxDynamicSharedMemorySize, SMEMT);

    float *p_pre, *p_ht, *p_qc, *p_kc, *p_vc, *p_mask;
    cudaGetSymbolAddress((void**)&p_pre,  g_pre);
    cudaGetSymbolAddress((void**)&p_ht,   g_ht);
    cudaGetSymbolAddress((void**)&p_qc,   g_qc);
    cudaGetSymbolAddress((void**)&p_kc,   g_kc);
    cudaGetSymbolAddress((void**)&p_vc,   g_vc);
    cudaGetSymbolAddress((void**)&p_mask, g_mask);
    bf16 *p_inp_h, *p_inp_l, *p_hs_h, *p_hs_l, *p_hth, *p_htl, *p_ctx_h, *p_ctx_l;
    cudaGetSymbolAddress((void**)&p_inp_h, g_inp_h);
    cudaGetSymbolAddress((void**)&p_inp_l, g_inp_l);
    cudaGetSymbolAddress((void**)&p_hs_h,  g_hs_h);
    cudaGetSymbolAddress((void**)&p_hs_l,  g_hs_l);
    cudaGetSymbolAddress((void**)&p_hth,   g_hth);
    cudaGetSymbolAddress((void**)&p_htl,   g_htl);
    cudaGetSymbolAddress((void**)&p_ctx_h, g_ctx_h);
    cudaGetSymbolAddress((void**)&p_ctx_l, g_ctx_l);
    bf16 *w_i2h_h, *w_i2h_l, *w_h2h_h, *w_h2h_l, *w_qc_h, *w_qc_l,
         *w_kc_h, *w_kc_l, *w_vc_h, *w_vc_l, *w_co_h, *w_co_l;
    cudaGetSymbolAddress((void**)&w_i2h_h, g_i2h_h);
    cudaGetSymbolAddress((void**)&w_i2h_l, g_i2h_l);
    cudaGetSymbolAddress((void**)&w_h2h_h, g_h2h_h);
    cudaGetSymbolAddress((void**)&w_h2h_l, g_h2h_l);
    cudaGetSymbolAddress((void**)&w_qc_h,  g_qcw_h);
    cudaGetSymbolAddress((void**)&w_qc_l,  g_qcw_l);
    cudaGetSymbolAddress((void**)&w_kc_h,  g_kcw_h);
    cudaGetSymbolAddress((void**)&w_kc_l,  g_kcw_l);
    cudaGetSymbolAddress((void**)&w_vc_h,  g_vcw_h);
    cudaGetSymbolAddress((void**)&w_vc_l,  g_vcw_l);
    cudaGetSymbolAddress((void**)&w_co_h,  g_cow_h);
    cudaGetSymbolAddress((void**)&w_co_l,  g_cow_l);

    // 1: single-launch weight split
    wsplit_all<<<(B6 + 255) / 256, 256>>>(h2h_w, qc_w, kc_w, vc_w, co_w, i2h_w);
    // 2-5: stage A
    kv_kernel<<<Bsz, 512>>>(x, key_w, key_b, value_w, value_b);
    qscore_kernel<<<Bsz * Uu, 64>>>(hs, query_w, key_b);
    topk_kernel<<<1, Bsz>>>();
    inphs_kernel<<<(INP_N + HS_N + 255) / 256, 256>>>(value_b, hs);

    // 6: preact = inp@i2h + hs@h2h (dual pass, K=416+512)  [ncu capture target]
    bgemm<<<dim3(2048 / 128, Bsz / 128, Uu), 256, SMEMT>>>(
        p_inp_h, p_inp_l, IVP, Uu * IVP, w_i2h_h, w_i2h_l, IVP,
        p_hs_h,  p_hs_l,  Hh,  Uu * Hh,  w_h2h_h, w_h2h_l, Hh,
        nullptr, nullptr,
        2048, p_pre, 0, nullptr, nullptr, nullptr, nullptr, nullptr, nullptr);

    // 7: gates
    gates_kernel<<<(Bsz * Uu * Hh + 255) / 256, 256>>>(cs, out_cs);

    // 8: qc + kc + vc in one launch (mode 3, grid.x = 18)
    bgemm<<<dim3(18, Bsz / 128, Uu), 256, SMEMT>>>(
        p_hth, p_htl, Hh, Uu * Hh, w_qc_h, w_qc_l, Hh,
        nullptr, nullptr, 0, 0, w_kc_h, w_kc_l, 0,
        w_vc_h, w_vc_l,
        128, p_qc, 3, p_kc, p_vc, nullptr, nullptr, nullptr, nullptr);

    // 9: attention
    attn_kernel<<<Bsz * NCHh, 256>>>();

    // 10: co GEMM with fused hs_new epilogue
    bgemm<<<dim3(512 / 128, Bsz / 128, Uu), 256, SMEMT>>>(
        p_ctx_h, p_ctx_l, NCHh * CVv, Uu * NCHh * CVv, w_co_h, w_co_l, NCHh * CVv,
        nullptr, nullptr, 0, 0, nullptr, nullptr, 0,
        nullptr, nullptr,
        512, nullptr, 1, nullptr, nullptr, p_ht, p_mask, hs, out_hs);
}